// round 15
// baseline (speedup 1.0000x reference)
#include <cuda_runtime.h>
#include <cuda_bf16.h>
#include <cstdint>

// Problem constants
#define B_  2
#define S_  2048
#define D_  512
#define H_  8
#define HD_ 64
#define T_  (B_*S_)      // 4096 tokens
#define FF_ (4*D_)       // 2048
#define QKV_N (3*D_)     // 1536

typedef __nv_bfloat16 bf16;

// ---------------------------------------------------------------------------
// Scratch (device globals; no allocation allowed)
// ---------------------------------------------------------------------------
__device__ bf16 g_xn_hi[T_*D_], g_xn_lo[T_*D_];             // LN out
__device__ bf16 g_qkvb_hi[3*T_*D_], g_qkvb_lo[3*T_*D_];     // head-major qkv
__device__ bf16 g_attn_hi[T_*D_], g_attn_lo[T_*D_];         // attention out [B,S,D]
__device__ bf16 g_h_hi[(size_t)T_*FF_], g_h_lo[(size_t)T_*FF_]; // MLP hidden
__device__ float g_bqkv[QKV_N];
// transposed+split weights: layout [N, K] bf16
__device__ bf16 g_wqkv_hi[QKV_N*D_], g_wqkv_lo[QKV_N*D_];
__device__ bf16 g_wp_hi[D_*D_], g_wp_lo[D_*D_];
__device__ bf16 g_w1_hi[D_*FF_], g_w1_lo[D_*FF_];
__device__ bf16 g_w2_hi[D_*FF_], g_w2_lo[D_*FF_];

// ---------------------------------------------------------------------------
// helpers
// ---------------------------------------------------------------------------
__device__ __forceinline__ uint32_t smem_to_u32(const void* p) {
    uint32_t a;
    asm("{ .reg .u64 tmp; cvta.to.shared.u64 tmp, %1; cvt.u32.u64 %0, tmp; }"
        : "=r"(a) : "l"(p));
    return a;
}
__device__ __forceinline__ void cp16(uint32_t smem, const void* g) {
    asm volatile("cp.async.ca.shared.global [%0], [%1], 16;" :: "r"(smem), "l"(g));
}
#define CP_COMMIT() asm volatile("cp.async.commit_group;" ::: "memory")
#define CP_WAIT2()  asm volatile("cp.async.wait_group 2;" ::: "memory")
#define CP_WAIT1()  asm volatile("cp.async.wait_group 1;" ::: "memory")
#define CP_WAIT0()  asm volatile("cp.async.wait_group 0;" ::: "memory")

__device__ __forceinline__ void ldsm_x4(uint32_t* r, uint32_t addr) {
    asm volatile("ldmatrix.sync.aligned.m8n8.x4.shared.b16 {%0,%1,%2,%3}, [%4];"
        : "=r"(r[0]), "=r"(r[1]), "=r"(r[2]), "=r"(r[3]) : "r"(addr));
}
__device__ __forceinline__ void ldsm_x4_t(uint32_t* r, uint32_t addr) {
    asm volatile("ldmatrix.sync.aligned.m8n8.x4.trans.shared.b16 {%0,%1,%2,%3}, [%4];"
        : "=r"(r[0]), "=r"(r[1]), "=r"(r[2]), "=r"(r[3]) : "r"(addr));
}
__device__ __forceinline__ void mma16816(float* c, const uint32_t* a, const uint32_t* b) {
    asm volatile("mma.sync.aligned.m16n8k16.row.col.f32.bf16.bf16.f32 "
        "{%0,%1,%2,%3}, {%4,%5,%6,%7}, {%8,%9}, {%0,%1,%2,%3};"
        : "+f"(c[0]), "+f"(c[1]), "+f"(c[2]), "+f"(c[3])
        : "r"(a[0]), "r"(a[1]), "r"(a[2]), "r"(a[3]), "r"(b[0]), "r"(b[1]));
}
__device__ __forceinline__ void split_bf16(float v, bf16& h, bf16& l) {
    h = __float2bfloat16(v);
    l = __float2bfloat16(v - __bfloat162float(h));
}
__device__ __forceinline__ uint32_t pack_bf2(float a, float b) {
    __nv_bfloat162 p;
    p.x = __float2bfloat16(a);
    p.y = __float2bfloat16(b);
    return *(uint32_t*)&p;
}
// swizzled byte offset within a 128row x 64B tile (rows of 4 x 16B groups)
__device__ __forceinline__ uint32_t sw_off(int row, int g) {
    return (uint32_t)(((row << 2) | (g ^ ((row >> 1) & 3))) << 4);
}

// ---------------------------------------------------------------------------
// LN row body (flat 256-thread block)
// ---------------------------------------------------------------------------
__device__ __forceinline__ void ln_row(const float* __restrict__ x, const float* __restrict__ g,
                                       const float* __restrict__ be, bf16* __restrict__ hi,
                                       bf16* __restrict__ lo, int row, int t) {
    const float* xr = x + (size_t)row * D_;
    float v0 = xr[t], v1 = xr[t + 256];
    float s = v0 + v1, ss = v0 * v0 + v1 * v1;
#pragma unroll
    for (int o = 16; o > 0; o >>= 1) {
        s  += __shfl_xor_sync(0xffffffffu, s, o);
        ss += __shfl_xor_sync(0xffffffffu, ss, o);
    }
    __shared__ float rs[8], rss[8];
    if ((t & 31) == 0) { rs[t >> 5] = s; rss[t >> 5] = ss; }
    __syncthreads();
    s = 0.f; ss = 0.f;
#pragma unroll
    for (int i = 0; i < 8; i++) { s += rs[i]; ss += rss[i]; }
    float mean = s * (1.f / (float)D_);
    float var  = ss * (1.f / (float)D_) - mean * mean;
    float r = rsqrtf(var + 1e-5f);
    float y0 = (v0 - mean) * r * g[t] + be[t];
    float y1 = (v1 - mean) * r * g[t + 256] + be[t + 256];
    bf16 h, l;
    split_bf16(y0, h, l); hi[(size_t)row * D_ + t] = h;       lo[(size_t)row * D_ + t] = l;
    split_bf16(y1, h, l); hi[(size_t)row * D_ + t + 256] = h; lo[(size_t)row * D_ + t + 256] = l;
}

// ---------------------------------------------------------------------------
// Fused prologue: weight transposes + bias pack + LN1 in ONE launch.
// ---------------------------------------------------------------------------
__global__ void convw_all(
    const float* __restrict__ Wq, const float* __restrict__ Wk, const float* __restrict__ Wv,
    const float* __restrict__ Wp, const float* __restrict__ W1, const float* __restrict__ W2,
    const float* __restrict__ bq, const float* __restrict__ bk, const float* __restrict__ bv,
    bf16* __restrict__ qkv_hi, bf16* __restrict__ qkv_lo,
    bf16* __restrict__ wp_hi, bf16* __restrict__ wp_lo,
    bf16* __restrict__ w1_hi, bf16* __restrict__ w1_lo,
    bf16* __restrict__ w2_hi, bf16* __restrict__ w2_lo,
    float* __restrict__ bqkv,
    const float* __restrict__ x, const float* __restrict__ g1,
    const float* __restrict__ be1, bf16* __restrict__ xn_hi, bf16* __restrict__ xn_lo) {
    int bid = blockIdx.x;
    int tx = threadIdx.x, ty = threadIdx.y;   // 32 x 8
    int ft = ty * 32 + tx;

    if (bid >= 3074) {                        // LN1 rows
        ln_row(x, g1, be1, xn_hi, xn_lo, bid - 3074, ft);
        return;
    }
    if (bid >= 3072) {                        // bias pack
        int t = (bid - 3072) * 256 + ft;
        if (t < D_) { bqkv[t] = bq[t]; bqkv[t + D_] = bk[t]; bqkv[t + 2 * D_] = bv[t]; }
        return;
    }

    const float* src; int sld; bf16 *dh, *dl; int dld; int kb, nb;
    if (bid < 768) {
        int w = bid >> 8, r = bid & 255;
        int h = r >> 5, rr = r & 31;
        int kbi = rr >> 1, nbi = rr & 1;
        const float* W = (w == 0) ? Wq : (w == 1) ? Wk : Wv;
        src = W + (size_t)h * D_ * HD_; sld = HD_;
        kb = kbi * 32; nb = nbi * 32;
        size_t rowoff = ((size_t)w * D_ + h * HD_) * D_;
        dh = qkv_hi + rowoff; dl = qkv_lo + rowoff; dld = D_;
    } else if (bid < 1024) {
        int r = bid - 768;
        kb = (r >> 4) * 32; nb = (r & 15) * 32;
        src = Wp; sld = D_; dh = wp_hi; dl = wp_lo; dld = D_;
    } else if (bid < 2048) {
        int r = bid - 1024;
        kb = (r >> 6) * 32; nb = (r & 63) * 32;
        src = W1; sld = FF_; dh = w1_hi; dl = w1_lo; dld = D_;
    } else {
        int r = bid - 2048;
        kb = (r >> 4) * 32; nb = (r & 15) * 32;
        src = W2; sld = D_; dh = w2_hi; dl = w2_lo; dld = FF_;
    }

    __shared__ float t[32][33];
#pragma unroll
    for (int i = 0; i < 32; i += 8) t[ty + i][tx] = src[(size_t)(kb + ty + i) * sld + nb + tx];
    __syncthreads();
#pragma unroll
    for (int i = 0; i < 32; i += 8) {
        float v = t[tx][ty + i];
        size_t o = (size_t)(nb + ty + i) * dld + kb + tx;
        bf16 h, l; split_bf16(v, h, l);
        dh[o] = h; dl[o] = l;
    }
}

// ---------------------------------------------------------------------------
// Standalone LN (for LN2).
// ---------------------------------------------------------------------------
__global__ void ln_kernel(const float* __restrict__ x, const float* __restrict__ g,
                          const float* __restrict__ be, bf16* __restrict__ hi,
                          bf16* __restrict__ lo) {
    ln_row(x, g, be, hi, lo, blockIdx.x, threadIdx.x);
}

// ---------------------------------------------------------------------------
// mma.sync GEMM, bf16x3, 3-stage cp.async pipeline. R11 winner config:
// 256 threads, warp grid 2(m)x4(n), warp tile 64x32, 2 CTA/SM.
// ---------------------------------------------------------------------------
#define SMT_AHI 0
#define SMT_ALO 8192
#define SMT_BHI 16384
#define SMT_BLO 24576
#define GSTAGE  32768
#define GEMM_SMEM (3*GSTAGE)

template <int MODE, bool RELU, bool RES>
__global__ void __launch_bounds__(256, 2) mma_gemm(
    const bf16* __restrict__ Ahi, const bf16* __restrict__ Alo,
    const bf16* __restrict__ Bhi, const bf16* __restrict__ Blo,
    const float* __restrict__ bias, const float* __restrict__ res,
    float* __restrict__ Cf, bf16* __restrict__ Chi, bf16* __restrict__ Clo,
    int M, int N, int K) {
    extern __shared__ __align__(128) char smem_buf[];
    uint32_t sb = smem_to_u32(smem_buf);
    int tid = threadIdx.x, lane = tid & 31, wid = tid >> 5;
    int wm = wid >> 2, wn = wid & 3;
    int m0 = blockIdx.y * 128, n0 = blockIdx.x * 128;

    float acc[4][4][4];
#pragma unroll
    for (int a = 0; a < 4; a++)
#pragma unroll
        for (int b = 0; b < 4; b++)
#pragma unroll
            for (int cc = 0; cc < 4; cc++) acc[a][b][cc] = 0.f;

    int ldrow = tid >> 2, ldg_ = tid & 3;
    int nchunk = K >> 5;

    auto issue = [&](int c) {
        int k0 = c << 5;
        uint32_t base = sb + (uint32_t)(c % 3) * GSTAGE;
#pragma unroll
        for (int it = 0; it < 2; it++) {
            int row = ldrow + it * 64;
            uint32_t off = sw_off(row, ldg_);
            size_t ao = (size_t)(m0 + row) * K + k0 + ldg_ * 8;
            size_t bo = (size_t)(n0 + row) * K + k0 + ldg_ * 8;
            cp16(base + SMT_AHI + off, Ahi + ao);
            cp16(base + SMT_ALO + off, Alo + ao);
            cp16(base + SMT_BHI + off, Bhi + bo);
            cp16(base + SMT_BLO + off, Blo + bo);
        }
    };

    issue(0); CP_COMMIT();
    if (nchunk > 1) { issue(1); CP_COMMIT(); }
    for (int c = 0; c < nchunk; c++) {
        if (c + 2 < nchunk) { issue(c + 2); CP_COMMIT(); CP_WAIT2(); }
        else if (c + 1 < nchunk) CP_WAIT1();
        else CP_WAIT0();
        __syncthreads();
        uint32_t base = sb + (uint32_t)(c % 3) * GSTAGE;
#pragma unroll
        for (int ks = 0; ks < 2; ks++) {
            int kg = ks * 2;
            uint32_t bh[4][2], bl[4][2];
#pragma unroll
            for (int ntp = 0; ntp < 2; ntp++) {
                int nrow = wn * 32 + ntp * 16 + (lane & 7) + ((lane >> 4) & 1) * 8;
                int bg = kg + ((lane >> 3) & 1);
                uint32_t off = sw_off(nrow, bg);
                uint32_t t4[4];
                ldsm_x4(t4, base + SMT_BHI + off);
                bh[ntp * 2][0] = t4[0]; bh[ntp * 2][1] = t4[1];
                bh[ntp * 2 + 1][0] = t4[2]; bh[ntp * 2 + 1][1] = t4[3];
                ldsm_x4(t4, base + SMT_BLO + off);
                bl[ntp * 2][0] = t4[0]; bl[ntp * 2][1] = t4[1];
                bl[ntp * 2 + 1][0] = t4[2]; bl[ntp * 2 + 1][1] = t4[3];
            }
#pragma unroll
            for (int mt = 0; mt < 4; mt++) {
                int arow = wm * 64 + mt * 16 + (lane & 7) + ((lane >> 3) & 1) * 8;
                int ag = kg + (lane >> 4);
                uint32_t off = sw_off(arow, ag);
                uint32_t ah[4], al[4];
                ldsm_x4(ah, base + SMT_AHI + off);
                ldsm_x4(al, base + SMT_ALO + off);
#pragma unroll
                for (int nt = 0; nt < 4; nt++) {
                    mma16816(acc[mt][nt], ah, bh[nt]);
                    mma16816(acc[mt][nt], ah, bl[nt]);
                    mma16816(acc[mt][nt], al, bh[nt]);
                }
            }
        }
        __syncthreads();
    }

#pragma unroll
    for (int mt = 0; mt < 4; mt++) {
#pragma unroll
        for (int nt = 0; nt < 4; nt++) {
            int r0 = m0 + wm * 64 + mt * 16 + (lane >> 2);
            int col = n0 + wn * 32 + nt * 8 + (lane & 3) * 2;
            float b0 = __ldg(bias + col), b1 = __ldg(bias + col + 1);
            float v00 = acc[mt][nt][0] + b0, v01 = acc[mt][nt][1] + b1;
            float v10 = acc[mt][nt][2] + b0, v11 = acc[mt][nt][3] + b1;
            if (RELU) {
                v00 = fmaxf(v00, 0.f); v01 = fmaxf(v01, 0.f);
                v10 = fmaxf(v10, 0.f); v11 = fmaxf(v11, 0.f);
            }
            if (MODE == 0) {
                if (RES) {
                    float2 ra = *(const float2*)(res + (size_t)r0 * N + col);
                    float2 rb = *(const float2*)(res + (size_t)(r0 + 8) * N + col);
                    v00 += ra.x; v01 += ra.y; v10 += rb.x; v11 += rb.y;
                }
                float2 o0 = {v00, v01}, o1 = {v10, v11};
                *(float2*)(Cf + (size_t)r0 * N + col) = o0;
                *(float2*)(Cf + (size_t)(r0 + 8) * N + col) = o1;
            } else if (MODE == 1) {
                bf16 h, l;
                __nv_bfloat162 ph, pl;
                split_bf16(v00, h, l); ph.x = h; pl.x = l;
                split_bf16(v01, h, l); ph.y = h; pl.y = l;
                *(__nv_bfloat162*)(Chi + (size_t)r0 * N + col) = ph;
                *(__nv_bfloat162*)(Clo + (size_t)r0 * N + col) = pl;
                split_bf16(v10, h, l); ph.x = h; pl.x = l;
                split_bf16(v11, h, l); ph.y = h; pl.y = l;
                *(__nv_bfloat162*)(Chi + (size_t)(r0 + 8) * N + col) = ph;
                *(__nv_bfloat162*)(Clo + (size_t)(r0 + 8) * N + col) = pl;
            } else {
                int which = col >> 9, rem = col & 511;
                int hh2 = rem >> 6, e = rem & 63;
#pragma unroll
                for (int rr = 0; rr < 2; rr++) {
                    int t = r0 + rr * 8;
                    float va = rr ? v10 : v00, vb = rr ? v11 : v01;
                    size_t off = (size_t)which * (T_ * (size_t)D_) +
                                 (((size_t)(t >> 11) * H_ + hh2) * S_ + (t & (S_ - 1))) * HD_ + e;
                    bf16 h, l;
                    __nv_bfloat162 ph, pl;
                    split_bf16(va, h, l); ph.x = h; pl.x = l;
                    split_bf16(vb, h, l); ph.y = h; pl.y = l;
                    *(__nv_bfloat162*)(Chi + off) = ph;
                    *(__nv_bfloat162*)(Clo + off) = pl;
                }
            }
        }
    }
}

// ---------------------------------------------------------------------------
// Flash attention, tensor cores, bf16x3. Q-tile 256 rows, 512 threads as
// TWO INDEPENDENT 8-warp groups: group g owns Q rows g*128..g*128+127 with
// its OWN KV pipeline (own smem stages, own named barriers, own cp.async
// groups). Groups run phase-decorrelated: one group's softmax overlaps the
// other's MMAs. KV loaded once per group (L2-served).
// ---------------------------------------------------------------------------
#define FPAD 72                          // bf16 per row (144 B)
#define FROW (FPAD*2)                    // 144 B
#define FTILE (64*FROW)                  // 9216 B per tile
#define FSTG (4*FTILE)                   // K_HI,K_LO,V_HI,V_LO = 36864 B/stage
#define GRP_SMEM (2*FSTG)                // 73728 B per group (2 stages)
#define QLO_BASE (2*GRP_SMEM)            // 147456: persistent Q-lo (256 rows)
#define FLASH_SMEM (QLO_BASE + 256*FROW) // 184320 B

#define GBAR(id) asm volatile("bar.sync %0, 256;" :: "r"(id) : "memory")

__global__ void __launch_bounds__(512, 1) flash_mma_kernel(
    const bf16* __restrict__ Phi, const bf16* __restrict__ Plo,
    bf16* __restrict__ Ohi, bf16* __restrict__ Olo) {
    extern __shared__ __align__(16) char fsm[];
    uint32_t sb = smem_to_u32(fsm);
    int tid = threadIdx.x, lane = tid & 31, wid = tid >> 5;
    int gid = wid >> 3, wl = wid & 7;      // group 0/1, warp-in-group 0..7
    int gtid = tid & 255;                  // thread-in-group
    int bh = blockIdx.y;
    int b_ = bh >> 3, h = bh & 7;
    int q0 = blockIdx.x * 256;

    size_t headoff = ((size_t)(b_ * H_ + h) * S_) * HD_;
    const bf16* Qh = Phi + headoff + (size_t)q0 * HD_;
    const bf16* Ql = Plo + headoff + (size_t)q0 * HD_;
    const bf16* Kh = Phi + (size_t)T_ * D_ + headoff;
    const bf16* Kl = Plo + (size_t)T_ * D_ + headoff;
    const bf16* Vh = Phi + 2 * (size_t)T_ * D_ + headoff;
    const bf16* Vl = Plo + 2 * (size_t)T_ * D_ + headoff;

    // --- stage Q: hi transient at base (fits group A's region); lo persistent ---
#pragma unroll
    for (int it = 0; it < 4; it++) {
        int idx = it * 512 + tid;          // 0..2047 -> 256 rows x 8 groups
        int row = idx >> 3, fg = idx & 7;
        uint32_t off = (uint32_t)(row * FROW + fg * 16);
        *(uint4*)(fsm + off)            = *(const uint4*)(Qh + (size_t)row * HD_ + fg * 8);
        *(uint4*)(fsm + QLO_BASE + off) = *(const uint4*)(Ql + (size_t)row * HD_ + fg * 8);
    }
    __syncthreads();
    uint32_t qh[4][4];
    int arow = gid * 128 + wl * 16 + (lane & 7) + ((lane >> 3) & 1) * 8;
    uint32_t qfr_off[4];
#pragma unroll
    for (int ks = 0; ks < 4; ks++) {
        qfr_off[ks] = (uint32_t)(arow * FROW + (ks * 2 + (lane >> 4)) * 16);
        ldsm_x4(qh[ks], sb + qfr_off[ks]);
    }
    __syncthreads();   // Q-hi region about to be overwritten by group A's KV

    uint32_t gbase = sb + (uint32_t)gid * GRP_SMEM;
    auto issueKV = [&](int kv, int st) {
        uint32_t bs = gbase + (uint32_t)st * FSTG;
#pragma unroll
        for (int it = 0; it < 2; it++) {
            int idx = it * 256 + gtid;     // 0..511 -> 64 rows x 8 groups
            int row = idx >> 3, fg = idx & 7;
            uint32_t off = (uint32_t)(row * FROW + fg * 16);
            size_t go = (size_t)(kv + row) * HD_ + fg * 8;
            cp16(bs + off,             Kh + go);
            cp16(bs + FTILE + off,     Kl + go);
            cp16(bs + 2 * FTILE + off, Vh + go);
            cp16(bs + 3 * FTILE + off, Vl + go);
        }
    };

    float m0 = -1e30f, m1 = -1e30f, l0 = 0.f, l1 = 0.f;
    float oacc[8][4];
#pragma unroll
    for (int i = 0; i < 8; i++)
#pragma unroll
        for (int j = 0; j < 4; j++) oacc[i][j] = 0.f;

    issueKV(0, 0);
    CP_COMMIT();
    int ntile = S_ / 64;
    for (int ti = 0; ti < ntile; ti++) {
        int st = ti & 1;
        if (ti + 1 < ntile) { issueKV((ti + 1) * 64, (ti + 1) & 1); CP_COMMIT(); CP_WAIT1(); }
        else CP_WAIT0();
        GBAR(gid + 1);
        uint32_t bs = gbase + (uint32_t)st * FSTG;

        // reload Q-lo fragments from persistent smem
        uint32_t ql[4][4];
#pragma unroll
        for (int ks = 0; ks < 4; ks++)
            ldsm_x4(ql[ks], sb + QLO_BASE + qfr_off[ks]);

        // --- S = Q K^T (8 n-tiles), bf16x3 ---
        float sacc[8][4];
#pragma unroll
        for (int i = 0; i < 8; i++)
#pragma unroll
            for (int j = 0; j < 4; j++) sacc[i][j] = 0.f;

#pragma unroll
        for (int ng = 0; ng < 4; ng++) {
            int nrow = ng * 16 + (lane & 7) + ((lane >> 4) & 1) * 8;
#pragma unroll
            for (int ks = 0; ks < 4; ks++) {
                int bg = ks * 2 + ((lane >> 3) & 1);
                uint32_t off = (uint32_t)(nrow * FROW + bg * 16);
                uint32_t th[4], tl[4];
                ldsm_x4(th, bs + off);
                ldsm_x4(tl, bs + FTILE + off);
                uint32_t bh0[2] = {th[0], th[1]}, bh1[2] = {th[2], th[3]};
                uint32_t bl0[2] = {tl[0], tl[1]}, bl1[2] = {tl[2], tl[3]};
                mma16816(sacc[ng * 2],     qh[ks], bh0);
                mma16816(sacc[ng * 2],     qh[ks], bl0);
                mma16816(sacc[ng * 2],     ql[ks], bh0);
                mma16816(sacc[ng * 2 + 1], qh[ks], bh1);
                mma16816(sacc[ng * 2 + 1], qh[ks], bl1);
                mma16816(sacc[ng * 2 + 1], ql[ks], bh1);
            }
        }

        // --- online softmax ---
        float rmax0 = -1e30f, rmax1 = -1e30f;
#pragma unroll
        for (int nt = 0; nt < 8; nt++) {
            rmax0 = fmaxf(rmax0, fmaxf(sacc[nt][0], sacc[nt][1]));
            rmax1 = fmaxf(rmax1, fmaxf(sacc[nt][2], sacc[nt][3]));
        }
        rmax0 = fmaxf(rmax0, __shfl_xor_sync(0xffffffffu, rmax0, 1));
        rmax0 = fmaxf(rmax0, __shfl_xor_sync(0xffffffffu, rmax0, 2));
        rmax1 = fmaxf(rmax1, __shfl_xor_sync(0xffffffffu, rmax1, 1));
        rmax1 = fmaxf(rmax1, __shfl_xor_sync(0xffffffffu, rmax1, 2));
        float mn0 = fmaxf(m0, rmax0), mn1 = fmaxf(m1, rmax1);
        float corr0 = __expf(m0 - mn0), corr1 = __expf(m1 - mn1);
        float ps0 = 0.f, ps1 = 0.f;
#pragma unroll
        for (int nt = 0; nt < 8; nt++) {
            sacc[nt][0] = __expf(sacc[nt][0] - mn0);
            sacc[nt][1] = __expf(sacc[nt][1] - mn0);
            sacc[nt][2] = __expf(sacc[nt][2] - mn1);
            sacc[nt][3] = __expf(sacc[nt][3] - mn1);
            ps0 += sacc[nt][0] + sacc[nt][1];
            ps1 += sacc[nt][2] + sacc[nt][3];
        }
        ps0 += __shfl_xor_sync(0xffffffffu, ps0, 1);
        ps0 += __shfl_xor_sync(0xffffffffu, ps0, 2);
        ps1 += __shfl_xor_sync(0xffffffffu, ps1, 1);
        ps1 += __shfl_xor_sync(0xffffffffu, ps1, 2);
        l0 = l0 * corr0 + ps0; l1 = l1 * corr1 + ps1;
        m0 = mn0; m1 = mn1;
#pragma unroll
        for (int i = 0; i < 8; i++) {
            oacc[i][0] *= corr0; oacc[i][1] *= corr0;
            oacc[i][2] *= corr1; oacc[i][3] *= corr1;
        }

        // --- O += P V (P from registers) ---
#pragma unroll
        for (int kc = 0; kc < 4; kc++) {
            float* pa = sacc[kc * 2];
            float* pb = sacc[kc * 2 + 1];
            uint32_t phi[4], plo[4];
            phi[0] = pack_bf2(pa[0], pa[1]);
            phi[1] = pack_bf2(pa[2], pa[3]);
            phi[2] = pack_bf2(pb[0], pb[1]);
            phi[3] = pack_bf2(pb[2], pb[3]);
            {
                __nv_bfloat162 h0 = *(__nv_bfloat162*)&phi[0];
                __nv_bfloat162 h1 = *(__nv_bfloat162*)&phi[1];
                __nv_bfloat162 h2 = *(__nv_bfloat162*)&phi[2];
                __nv_bfloat162 h3 = *(__nv_bfloat162*)&phi[3];
                plo[0] = pack_bf2(pa[0] - __bfloat162float(h0.x), pa[1] - __bfloat162float(h0.y));
                plo[1] = pack_bf2(pa[2] - __bfloat162float(h1.x), pa[3] - __bfloat162float(h1.y));
                plo[2] = pack_bf2(pb[0] - __bfloat162float(h2.x), pb[1] - __bfloat162float(h2.y));
                plo[3] = pack_bf2(pb[2] - __bfloat162float(h3.x), pb[3] - __bfloat162float(h3.y));
            }
#pragma unroll
            for (int hg = 0; hg < 4; hg++) {
                int vrow = kc * 16 + ((lane >> 3) & 1) * 8 + (lane & 7);
                int vcol = hg * 16 + ((lane >> 4) & 1) * 8;
                uint32_t off = (uint32_t)(vrow * FROW + vcol * 2);
                uint32_t th[4], tl[4];
                ldsm_x4_t(th, bs + 2 * FTILE + off);
                ldsm_x4_t(tl, bs + 3 * FTILE + off);
                uint32_t bh0[2] = {th[0], th[1]}, bh1[2] = {th[2], th[3]};
                uint32_t bl0[2] = {tl[0], tl[1]}, bl1[2] = {tl[2], tl[3]};
                mma16816(oacc[hg * 2],     phi, bh0);
                mma16816(oacc[hg * 2],     phi, bl0);
                mma16816(oacc[hg * 2],     plo, bh0);
                mma16816(oacc[hg * 2 + 1], phi, bh1);
                mma16816(oacc[hg * 2 + 1], phi, bl1);
                mma16816(oacc[hg * 2 + 1], plo, bh1);
            }
        }
        GBAR(gid + 1);   // done reading this stage before its next overwrite
    }

    // --- write O as bf16 hi/lo pairs, [B,S,D] concat layout ---
    float inv0 = 1.f / l0, inv1 = 1.f / l1;
    int r0 = q0 + gid * 128 + wl * 16 + (lane >> 2);
#pragma unroll
    for (int nt = 0; nt < 8; nt++) {
        int col = h * HD_ + nt * 8 + (lane & 3) * 2;
        float v00 = oacc[nt][0] * inv0, v01 = oacc[nt][1] * inv0;
        float v10 = oacc[nt][2] * inv1, v11 = oacc[nt][3] * inv1;
        bf16 hh, ll;
        __nv_bfloat162 ph, pl;
        split_bf16(v00, hh, ll); ph.x = hh; pl.x = ll;
        split_bf16(v01, hh, ll); ph.y = hh; pl.y = ll;
        *(__nv_bfloat162*)(Ohi + ((size_t)b_ * S_ + r0) * D_ + col) = ph;
        *(__nv_bfloat162*)(Olo + ((size_t)b_ * S_ + r0) * D_ + col) = pl;
        split_bf16(v10, hh, ll); ph.x = hh; pl.x = ll;
        split_bf16(v11, hh, ll); ph.y = hh; pl.y = ll;
        *(__nv_bfloat162*)(Ohi + ((size_t)b_ * S_ + r0 + 8) * D_ + col) = ph;
        *(__nv_bfloat162*)(Olo + ((size_t)b_ * S_ + r0 + 8) * D_ + col) = pl;
    }
}

// ---------------------------------------------------------------------------
// Launch
// ---------------------------------------------------------------------------
extern "C" void kernel_launch(void* const* d_in, const int* in_sizes, int n_in,
                              void* d_out, int out_size) {
    const float* x   = (const float*)d_in[0];
    const float* Wq  = (const float*)d_in[1];
    const float* bq  = (const float*)d_in[2];
    const float* Wk  = (const float*)d_in[3];
    const float* bk  = (const float*)d_in[4];
    const float* Wv  = (const float*)d_in[5];
    const float* bv  = (const float*)d_in[6];
    const float* Wp  = (const float*)d_in[7];
    const float* bp  = (const float*)d_in[8];
    const float* W1  = (const float*)d_in[9];
    const float* b1  = (const float*)d_in[10];
    const float* W2  = (const float*)d_in[11];
    const float* b2  = (const float*)d_in[12];
    const float* g1  = (const float*)d_in[13];
    const float* be1 = (const float*)d_in[14];
    const float* g2  = (const float*)d_in[15];
    const float* be2 = (const float*)d_in[16];
    float* out = (float*)d_out;

    bf16 *xn_hi, *xn_lo, *attn_hi, *attn_lo, *h_hi, *h_lo, *qb_hi, *qb_lo;
    bf16 *wqkv_hi, *wqkv_lo, *wp_hi, *wp_lo, *w1_hi, *w1_lo, *w2_hi, *w2_lo;
    float *bqkv;
    cudaGetSymbolAddress((void**)&xn_hi, g_xn_hi);     cudaGetSymbolAddress((void**)&xn_lo, g_xn_lo);
    cudaGetSymbolAddress((void**)&attn_hi, g_attn_hi); cudaGetSymbolAddress((void**)&attn_lo, g_attn_lo);
    cudaGetSymbolAddress((void**)&h_hi, g_h_hi);       cudaGetSymbolAddress((void**)&h_lo, g_h_lo);
    cudaGetSymbolAddress((void**)&qb_hi, g_qkvb_hi);   cudaGetSymbolAddress((void**)&qb_lo, g_qkvb_lo);
    cudaGetSymbolAddress((void**)&wqkv_hi, g_wqkv_hi); cudaGetSymbolAddress((void**)&wqkv_lo, g_wqkv_lo);
    cudaGetSymbolAddress((void**)&wp_hi, g_wp_hi);     cudaGetSymbolAddress((void**)&wp_lo, g_wp_lo);
    cudaGetSymbolAddress((void**)&w1_hi, g_w1_hi);     cudaGetSymbolAddress((void**)&w1_lo, g_w1_lo);
    cudaGetSymbolAddress((void**)&w2_hi, g_w2_hi);     cudaGetSymbolAddress((void**)&w2_lo, g_w2_lo);
    cudaGetSymbolAddress((void**)&bqkv, g_bqkv);

    cudaFuncSetAttribute(mma_gemm<2, false, false>, cudaFuncAttributeMaxDynamicSharedMemorySize, GEMM_SMEM);
    cudaFuncSetAttribute(mma_gemm<0, false, true>,  cudaFuncAttributeMaxDynamicSharedMemorySize, GEMM_SMEM);
    cudaFuncSetAttribute(mma_gemm<1, true, false>,  cudaFuncAttributeMaxDynamicSharedMemorySize, GEMM_SMEM);
    cudaFuncSetAttribute(flash_mma_kernel, cudaFuncAttributeMaxDynamicSharedMemorySize, FLASH_SMEM);

    // weight conversions + bias pack + LN1, one launch
    convw_all<<<3074 + T_, dim3(32, 8)>>>(Wq, Wk, Wv, Wp, W1, W2, bq, bk, bv,
                                          wqkv_hi, wqkv_lo, wp_hi, wp_lo,
                                          w1_hi, w1_lo, w2_hi, w2_lo, bqkv,
                                          x, g1, be1, xn_hi, xn_lo);

    // fused QKV GEMM -> bf16 pairs, head-major scatter
    mma_gemm<2, false, false><<<dim3(QKV_N / 128, T_ / 128), 256, GEMM_SMEM>>>(
        xn_hi, xn_lo, wqkv_hi, wqkv_lo, bqkv, nullptr, nullptr, qb_hi, qb_lo, T_, QKV_N, D_);

    // flash attention (two phase-decorrelated warp groups per CTA)
    flash_mma_kernel<<<dim3(S_ / 256, B_ * H_), 512, FLASH_SMEM>>>(qb_hi, qb_lo, attn_hi, attn_lo);

    // proj + residual: out = x + attn @ Wp + bp
    mma_gemm<0, false, true><<<dim3(D_ / 128, T_ / 128), 256, GEMM_SMEM>>>(
        attn_hi, attn_lo, wp_hi, wp_lo, bp, x, out, nullptr, nullptr, T_, D_, D_);

    // LN2
    ln_kernel<<<T_, 256>>>(out, g2, be2, xn_hi, xn_lo);

    // MLP1 (ReLU) -> h bf16 pair
    mma_gemm<1, true, false><<<dim3(FF_ / 128, T_ / 128), 256, GEMM_SMEM>>>(
        xn_hi, xn_lo, w1_hi, w1_lo, b1, nullptr, nullptr, h_hi, h_lo, T_, FF_, D_);

    // MLP2 + residual (in place on out)
    mma_gemm<0, false, true><<<dim3(D_ / 128, T_ / 128), 256, GEMM_SMEM>>>(
        h_hi, h_lo, w2_hi, w2_lo, b2, out, out, nullptr, nullptr, T_, D_, FF_);
}

// round 16
// speedup vs baseline: 1.0072x; 1.0072x over previous
#include <cuda_runtime.h>
#include <cuda_bf16.h>
#include <cstdint>

// Problem constants
#define B_  2
#define S_  2048
#define D_  512
#define H_  8
#define HD_ 64
#define T_  (B_*S_)      // 4096 tokens
#define FF_ (4*D_)       // 2048
#define QKV_N (3*D_)     // 1536

typedef __nv_bfloat16 bf16;

// ---------------------------------------------------------------------------
// Scratch (device globals; no allocation allowed)
// ---------------------------------------------------------------------------
__device__ bf16 g_xn_hi[T_*D_], g_xn_lo[T_*D_];             // LN out
__device__ bf16 g_qkvb_hi[3*T_*D_], g_qkvb_lo[3*T_*D_];     // head-major qkv
__device__ bf16 g_attn_hi[T_*D_], g_attn_lo[T_*D_];         // attention out [B,S,D]
__device__ bf16 g_h_hi[(size_t)T_*FF_], g_h_lo[(size_t)T_*FF_]; // MLP hidden
__device__ float g_part[2*(size_t)T_*D_];                   // split-K partials
__device__ float g_bqkv[QKV_N];
// transposed+split weights: layout [N, K] bf16
__device__ bf16 g_wqkv_hi[QKV_N*D_], g_wqkv_lo[QKV_N*D_];
__device__ bf16 g_wp_hi[D_*D_], g_wp_lo[D_*D_];
__device__ bf16 g_w1_hi[D_*FF_], g_w1_lo[D_*FF_];
__device__ bf16 g_w2_hi[D_*FF_], g_w2_lo[D_*FF_];

// ---------------------------------------------------------------------------
// helpers
// ---------------------------------------------------------------------------
__device__ __forceinline__ uint32_t smem_to_u32(const void* p) {
    uint32_t a;
    asm("{ .reg .u64 tmp; cvta.to.shared.u64 tmp, %1; cvt.u32.u64 %0, tmp; }"
        : "=r"(a) : "l"(p));
    return a;
}
__device__ __forceinline__ void cp16(uint32_t smem, const void* g) {
    asm volatile("cp.async.ca.shared.global [%0], [%1], 16;" :: "r"(smem), "l"(g));
}
#define CP_COMMIT() asm volatile("cp.async.commit_group;" ::: "memory")
#define CP_WAIT2()  asm volatile("cp.async.wait_group 2;" ::: "memory")
#define CP_WAIT1()  asm volatile("cp.async.wait_group 1;" ::: "memory")
#define CP_WAIT0()  asm volatile("cp.async.wait_group 0;" ::: "memory")

__device__ __forceinline__ void ldsm_x4(uint32_t* r, uint32_t addr) {
    asm volatile("ldmatrix.sync.aligned.m8n8.x4.shared.b16 {%0,%1,%2,%3}, [%4];"
        : "=r"(r[0]), "=r"(r[1]), "=r"(r[2]), "=r"(r[3]) : "r"(addr));
}
__device__ __forceinline__ void ldsm_x4_t(uint32_t* r, uint32_t addr) {
    asm volatile("ldmatrix.sync.aligned.m8n8.x4.trans.shared.b16 {%0,%1,%2,%3}, [%4];"
        : "=r"(r[0]), "=r"(r[1]), "=r"(r[2]), "=r"(r[3]) : "r"(addr));
}
__device__ __forceinline__ void mma16816(float* c, const uint32_t* a, const uint32_t* b) {
    asm volatile("mma.sync.aligned.m16n8k16.row.col.f32.bf16.bf16.f32 "
        "{%0,%1,%2,%3}, {%4,%5,%6,%7}, {%8,%9}, {%0,%1,%2,%3};"
        : "+f"(c[0]), "+f"(c[1]), "+f"(c[2]), "+f"(c[3])
        : "r"(a[0]), "r"(a[1]), "r"(a[2]), "r"(a[3]), "r"(b[0]), "r"(b[1]));
}
__device__ __forceinline__ void split_bf16(float v, bf16& h, bf16& l) {
    h = __float2bfloat16(v);
    l = __float2bfloat16(v - __bfloat162float(h));
}
__device__ __forceinline__ uint32_t pack_bf2(float a, float b) {
    __nv_bfloat162 p;
    p.x = __float2bfloat16(a);
    p.y = __float2bfloat16(b);
    return *(uint32_t*)&p;
}
// swizzled byte offset within a 128row x 64B tile (rows of 4 x 16B groups)
__device__ __forceinline__ uint32_t sw_off(int row, int g) {
    return (uint32_t)(((row << 2) | (g ^ ((row >> 1) & 3))) << 4);
}

// ---------------------------------------------------------------------------
// LN row body (flat 256-thread block)
// ---------------------------------------------------------------------------
__device__ __forceinline__ void ln_row(const float* __restrict__ x, const float* __restrict__ g,
                                       const float* __restrict__ be, bf16* __restrict__ hi,
                                       bf16* __restrict__ lo, int row, int t) {
    const float* xr = x + (size_t)row * D_;
    float v0 = xr[t], v1 = xr[t + 256];
    float s = v0 + v1, ss = v0 * v0 + v1 * v1;
#pragma unroll
    for (int o = 16; o > 0; o >>= 1) {
        s  += __shfl_xor_sync(0xffffffffu, s, o);
        ss += __shfl_xor_sync(0xffffffffu, ss, o);
    }
    __shared__ float rs[8], rss[8];
    if ((t & 31) == 0) { rs[t >> 5] = s; rss[t >> 5] = ss; }
    __syncthreads();
    s = 0.f; ss = 0.f;
#pragma unroll
    for (int i = 0; i < 8; i++) { s += rs[i]; ss += rss[i]; }
    float mean = s * (1.f / (float)D_);
    float var  = ss * (1.f / (float)D_) - mean * mean;
    float r = rsqrtf(var + 1e-5f);
    float y0 = (v0 - mean) * r * g[t] + be[t];
    float y1 = (v1 - mean) * r * g[t + 256] + be[t + 256];
    bf16 h, l;
    split_bf16(y0, h, l); hi[(size_t)row * D_ + t] = h;       lo[(size_t)row * D_ + t] = l;
    split_bf16(y1, h, l); hi[(size_t)row * D_ + t + 256] = h; lo[(size_t)row * D_ + t + 256] = l;
}

// ---------------------------------------------------------------------------
// Fused prologue: weight transposes + bias pack + LN1 in ONE launch.
// ---------------------------------------------------------------------------
__global__ void convw_all(
    const float* __restrict__ Wq, const float* __restrict__ Wk, const float* __restrict__ Wv,
    const float* __restrict__ Wp, const float* __restrict__ W1, const float* __restrict__ W2,
    const float* __restrict__ bq, const float* __restrict__ bk, const float* __restrict__ bv,
    bf16* __restrict__ qkv_hi, bf16* __restrict__ qkv_lo,
    bf16* __restrict__ wp_hi, bf16* __restrict__ wp_lo,
    bf16* __restrict__ w1_hi, bf16* __restrict__ w1_lo,
    bf16* __restrict__ w2_hi, bf16* __restrict__ w2_lo,
    float* __restrict__ bqkv,
    const float* __restrict__ x, const float* __restrict__ g1,
    const float* __restrict__ be1, bf16* __restrict__ xn_hi, bf16* __restrict__ xn_lo) {
    int bid = blockIdx.x;
    int tx = threadIdx.x, ty = threadIdx.y;   // 32 x 8
    int ft = ty * 32 + tx;

    if (bid >= 3074) {                        // LN1 rows
        ln_row(x, g1, be1, xn_hi, xn_lo, bid - 3074, ft);
        return;
    }
    if (bid >= 3072) {                        // bias pack
        int t = (bid - 3072) * 256 + ft;
        if (t < D_) { bqkv[t] = bq[t]; bqkv[t + D_] = bk[t]; bqkv[t + 2 * D_] = bv[t]; }
        return;
    }

    const float* src; int sld; bf16 *dh, *dl; int dld; int kb, nb;
    if (bid < 768) {
        int w = bid >> 8, r = bid & 255;
        int h = r >> 5, rr = r & 31;
        int kbi = rr >> 1, nbi = rr & 1;
        const float* W = (w == 0) ? Wq : (w == 1) ? Wk : Wv;
        src = W + (size_t)h * D_ * HD_; sld = HD_;
        kb = kbi * 32; nb = nbi * 32;
        size_t rowoff = ((size_t)w * D_ + h * HD_) * D_;
        dh = qkv_hi + rowoff; dl = qkv_lo + rowoff; dld = D_;
    } else if (bid < 1024) {
        int r = bid - 768;
        kb = (r >> 4) * 32; nb = (r & 15) * 32;
        src = Wp; sld = D_; dh = wp_hi; dl = wp_lo; dld = D_;
    } else if (bid < 2048) {
        int r = bid - 1024;
        kb = (r >> 6) * 32; nb = (r & 63) * 32;
        src = W1; sld = FF_; dh = w1_hi; dl = w1_lo; dld = D_;
    } else {
        int r = bid - 2048;
        kb = (r >> 4) * 32; nb = (r & 15) * 32;
        src = W2; sld = D_; dh = w2_hi; dl = w2_lo; dld = FF_;
    }

    __shared__ float t[32][33];
#pragma unroll
    for (int i = 0; i < 32; i += 8) t[ty + i][tx] = src[(size_t)(kb + ty + i) * sld + nb + tx];
    __syncthreads();
#pragma unroll
    for (int i = 0; i < 32; i += 8) {
        float v = t[tx][ty + i];
        size_t o = (size_t)(nb + ty + i) * dld + kb + tx;
        bf16 h, l; split_bf16(v, h, l);
        dh[o] = h; dl[o] = l;
    }
}

// ---------------------------------------------------------------------------
// Standalone LN (for LN2).
// ---------------------------------------------------------------------------
__global__ void ln_kernel(const float* __restrict__ x, const float* __restrict__ g,
                          const float* __restrict__ be, bf16* __restrict__ hi,
                          bf16* __restrict__ lo) {
    ln_row(x, g, be, hi, lo, blockIdx.x, threadIdx.x);
}

// ---------------------------------------------------------------------------
// Split-K reduce: out = part0 + part1 + bias + res. float4 per thread.
// ---------------------------------------------------------------------------
__global__ void reduce_splitk(const float* __restrict__ part, const float* __restrict__ bias,
                              const float* __restrict__ res, float* __restrict__ out) {
    size_t i = ((size_t)blockIdx.x * 256 + threadIdx.x) * 4;
    float4 a = *(const float4*)(part + i);
    float4 b = *(const float4*)(part + (size_t)T_ * D_ + i);
    float4 r = *(const float4*)(res + i);
    int col = (int)(i & (D_ - 1));
    float4 bs = *(const float4*)(bias + col);
    float4 o;
    o.x = a.x + b.x + r.x + bs.x;
    o.y = a.y + b.y + r.y + bs.y;
    o.z = a.z + b.z + r.z + bs.z;
    o.w = a.w + b.w + r.w + bs.w;
    *(float4*)(out + i) = o;
}

// ---------------------------------------------------------------------------
// mma.sync GEMM, bf16x3, 3-stage cp.async pipeline. R11 winner config:
// 256 threads, warp grid 2(m)x4(n), warp tile 64x32, 2 CTA/SM.
// MODE 0: fp32 out (+res). MODE 1: bf16 pair out (RELU opt). MODE 2: qkv
// scatter. MODE 3: split-K partial (gridDim.z=2, raw fp32 to Cf+z*M*N).
// ---------------------------------------------------------------------------
#define SMT_AHI 0
#define SMT_ALO 8192
#define SMT_BHI 16384
#define SMT_BLO 24576
#define GSTAGE  32768
#define GEMM_SMEM (3*GSTAGE)

template <int MODE, bool RELU, bool RES>
__global__ void __launch_bounds__(256, 2) mma_gemm(
    const bf16* __restrict__ Ahi, const bf16* __restrict__ Alo,
    const bf16* __restrict__ Bhi, const bf16* __restrict__ Blo,
    const float* __restrict__ bias, const float* __restrict__ res,
    float* __restrict__ Cf, bf16* __restrict__ Chi, bf16* __restrict__ Clo,
    int M, int N, int K) {
    extern __shared__ __align__(128) char smem_buf[];
    uint32_t sb = smem_to_u32(smem_buf);
    int tid = threadIdx.x, lane = tid & 31, wid = tid >> 5;
    int wm = wid >> 2, wn = wid & 3;
    int m0 = blockIdx.y * 128, n0 = blockIdx.x * 128;
    int kbase = (MODE == 3) ? (int)blockIdx.z * (K >> 1) : 0;
    int klen  = (MODE == 3) ? (K >> 1) : K;

    float acc[4][4][4];
#pragma unroll
    for (int a = 0; a < 4; a++)
#pragma unroll
        for (int b = 0; b < 4; b++)
#pragma unroll
            for (int cc = 0; cc < 4; cc++) acc[a][b][cc] = 0.f;

    int ldrow = tid >> 2, ldg_ = tid & 3;
    int nchunk = klen >> 5;

    auto issue = [&](int c) {
        int k0 = kbase + (c << 5);
        uint32_t base = sb + (uint32_t)(c % 3) * GSTAGE;
#pragma unroll
        for (int it = 0; it < 2; it++) {
            int row = ldrow + it * 64;
            uint32_t off = sw_off(row, ldg_);
            size_t ao = (size_t)(m0 + row) * K + k0 + ldg_ * 8;
            size_t bo = (size_t)(n0 + row) * K + k0 + ldg_ * 8;
            cp16(base + SMT_AHI + off, Ahi + ao);
            cp16(base + SMT_ALO + off, Alo + ao);
            cp16(base + SMT_BHI + off, Bhi + bo);
            cp16(base + SMT_BLO + off, Blo + bo);
        }
    };

    issue(0); CP_COMMIT();
    if (nchunk > 1) { issue(1); CP_COMMIT(); }
    for (int c = 0; c < nchunk; c++) {
        if (c + 2 < nchunk) { issue(c + 2); CP_COMMIT(); CP_WAIT2(); }
        else if (c + 1 < nchunk) CP_WAIT1();
        else CP_WAIT0();
        __syncthreads();
        uint32_t base = sb + (uint32_t)(c % 3) * GSTAGE;
#pragma unroll
        for (int ks = 0; ks < 2; ks++) {
            int kg = ks * 2;
            uint32_t bh[4][2], bl[4][2];
#pragma unroll
            for (int ntp = 0; ntp < 2; ntp++) {
                int nrow = wn * 32 + ntp * 16 + (lane & 7) + ((lane >> 4) & 1) * 8;
                int bg = kg + ((lane >> 3) & 1);
                uint32_t off = sw_off(nrow, bg);
                uint32_t t4[4];
                ldsm_x4(t4, base + SMT_BHI + off);
                bh[ntp * 2][0] = t4[0]; bh[ntp * 2][1] = t4[1];
                bh[ntp * 2 + 1][0] = t4[2]; bh[ntp * 2 + 1][1] = t4[3];
                ldsm_x4(t4, base + SMT_BLO + off);
                bl[ntp * 2][0] = t4[0]; bl[ntp * 2][1] = t4[1];
                bl[ntp * 2 + 1][0] = t4[2]; bl[ntp * 2 + 1][1] = t4[3];
            }
#pragma unroll
            for (int mt = 0; mt < 4; mt++) {
                int arow = wm * 64 + mt * 16 + (lane & 7) + ((lane >> 3) & 1) * 8;
                int ag = kg + (lane >> 4);
                uint32_t off = sw_off(arow, ag);
                uint32_t ah[4], al[4];
                ldsm_x4(ah, base + SMT_AHI + off);
                ldsm_x4(al, base + SMT_ALO + off);
#pragma unroll
                for (int nt = 0; nt < 4; nt++) {
                    mma16816(acc[mt][nt], ah, bh[nt]);
                    mma16816(acc[mt][nt], ah, bl[nt]);
                    mma16816(acc[mt][nt], al, bh[nt]);
                }
            }
        }
        __syncthreads();
    }

#pragma unroll
    for (int mt = 0; mt < 4; mt++) {
#pragma unroll
        for (int nt = 0; nt < 4; nt++) {
            int r0 = m0 + wm * 64 + mt * 16 + (lane >> 2);
            int col = n0 + wn * 32 + nt * 8 + (lane & 3) * 2;
            if (MODE == 3) {
                float* dst = Cf + (size_t)blockIdx.z * M * N;
                float2 o0 = {acc[mt][nt][0], acc[mt][nt][1]};
                float2 o1 = {acc[mt][nt][2], acc[mt][nt][3]};
                *(float2*)(dst + (size_t)r0 * N + col) = o0;
                *(float2*)(dst + (size_t)(r0 + 8) * N + col) = o1;
                continue;
            }
            float b0 = __ldg(bias + col), b1 = __ldg(bias + col + 1);
            float v00 = acc[mt][nt][0] + b0, v01 = acc[mt][nt][1] + b1;
            float v10 = acc[mt][nt][2] + b0, v11 = acc[mt][nt][3] + b1;
            if (RELU) {
                v00 = fmaxf(v00, 0.f); v01 = fmaxf(v01, 0.f);
                v10 = fmaxf(v10, 0.f); v11 = fmaxf(v11, 0.f);
            }
            if (MODE == 0) {
                if (RES) {
                    float2 ra = *(const float2*)(res + (size_t)r0 * N + col);
                    float2 rb = *(const float2*)(res + (size_t)(r0 + 8) * N + col);
                    v00 += ra.x; v01 += ra.y; v10 += rb.x; v11 += rb.y;
                }
                float2 o0 = {v00, v01}, o1 = {v10, v11};
                *(float2*)(Cf + (size_t)r0 * N + col) = o0;
                *(float2*)(Cf + (size_t)(r0 + 8) * N + col) = o1;
            } else if (MODE == 1) {
                bf16 h, l;
                __nv_bfloat162 ph, pl;
                split_bf16(v00, h, l); ph.x = h; pl.x = l;
                split_bf16(v01, h, l); ph.y = h; pl.y = l;
                *(__nv_bfloat162*)(Chi + (size_t)r0 * N + col) = ph;
                *(__nv_bfloat162*)(Clo + (size_t)r0 * N + col) = pl;
                split_bf16(v10, h, l); ph.x = h; pl.x = l;
                split_bf16(v11, h, l); ph.y = h; pl.y = l;
                *(__nv_bfloat162*)(Chi + (size_t)(r0 + 8) * N + col) = ph;
                *(__nv_bfloat162*)(Clo + (size_t)(r0 + 8) * N + col) = pl;
            } else {
                int which = col >> 9, rem = col & 511;
                int hh2 = rem >> 6, e = rem & 63;
#pragma unroll
                for (int rr = 0; rr < 2; rr++) {
                    int t = r0 + rr * 8;
                    float va = rr ? v10 : v00, vb = rr ? v11 : v01;
                    size_t off = (size_t)which * (T_ * (size_t)D_) +
                                 (((size_t)(t >> 11) * H_ + hh2) * S_ + (t & (S_ - 1))) * HD_ + e;
                    bf16 h, l;
                    __nv_bfloat162 ph, pl;
                    split_bf16(va, h, l); ph.x = h; pl.x = l;
                    split_bf16(vb, h, l); ph.y = h; pl.y = l;
                    *(__nv_bfloat162*)(Chi + off) = ph;
                    *(__nv_bfloat162*)(Clo + off) = pl;
                }
            }
        }
    }
}

// ---------------------------------------------------------------------------
// Flash attention, tensor cores, bf16x3 (R13 428.0 version). Q-tile 256 rows,
// 512 threads, Q-lo persistent in smem. KV staged 128 rows per cp.async
// group (2 stages), computed as two 64-row halves.
// ---------------------------------------------------------------------------
#define FPAD 72                          // bf16 per row (144 B)
#define FROW (FPAD*2)                    // 144 B
#define FHALF (64*FROW)                  // 9216 B (64-row half-tile)
#define FT2 (128*FROW)                   // 18432 B (128-row tile)
#define FSTAGE (4*FT2)                   // K_HI,K_LO,V_HI,V_LO = 73728 B
#define QLO_BASE (2*FSTAGE)              // persistent Q-lo region (256 rows)
#define FLASH_SMEM (2*FSTAGE + 256*FROW) // 184320 B

__global__ void __launch_bounds__(512, 1) flash_mma_kernel(
    const bf16* __restrict__ Phi, const bf16* __restrict__ Plo,
    bf16* __restrict__ Ohi, bf16* __restrict__ Olo) {
    extern __shared__ __align__(16) char fsm[];
    uint32_t sb = smem_to_u32(fsm);
    int tid = threadIdx.x, lane = tid & 31, wid = tid >> 5;
    int bh = blockIdx.y;
    int b_ = bh >> 3, h = bh & 7;
    int q0 = blockIdx.x * 256;

    size_t headoff = ((size_t)(b_ * H_ + h) * S_) * HD_;
    const bf16* Qh = Phi + headoff + (size_t)q0 * HD_;
    const bf16* Ql = Plo + headoff + (size_t)q0 * HD_;
    const bf16* Kh = Phi + (size_t)T_ * D_ + headoff;
    const bf16* Kl = Plo + (size_t)T_ * D_ + headoff;
    const bf16* Vh = Phi + 2 * (size_t)T_ * D_ + headoff;
    const bf16* Vl = Plo + 2 * (size_t)T_ * D_ + headoff;

#pragma unroll
    for (int it = 0; it < 4; it++) {
        int idx = it * 512 + tid;          // 0..2047
        int row = idx >> 3, fg = idx & 7;
        uint32_t off = (uint32_t)(row * FROW + fg * 16);
        *(uint4*)(fsm + off)            = *(const uint4*)(Qh + (size_t)row * HD_ + fg * 8);
        *(uint4*)(fsm + QLO_BASE + off) = *(const uint4*)(Ql + (size_t)row * HD_ + fg * 8);
    }
    __syncthreads();
    uint32_t qh[4][4];
    int arow = wid * 16 + (lane & 7) + ((lane >> 3) & 1) * 8;
    uint32_t qfr_off[4];
#pragma unroll
    for (int ks = 0; ks < 4; ks++) {
        qfr_off[ks] = (uint32_t)(arow * FROW + (ks * 2 + (lane >> 4)) * 16);
        ldsm_x4(qh[ks], sb + qfr_off[ks]);
    }
    __syncthreads();

    auto issueKV = [&](int kv, int st) {
        uint32_t bs = sb + (uint32_t)st * FSTAGE;
#pragma unroll
        for (int it = 0; it < 2; it++) {
            int idx = it * 512 + tid;      // 0..1023 -> 128 rows x 8 groups
            int row = idx >> 3, fg = idx & 7;
            uint32_t off = (uint32_t)(row * FROW + fg * 16);
            size_t go = (size_t)(kv + row) * HD_ + fg * 8;
            cp16(bs + off,           Kh + go);
            cp16(bs + FT2 + off,     Kl + go);
            cp16(bs + 2 * FT2 + off, Vh + go);
            cp16(bs + 3 * FT2 + off, Vl + go);
        }
    };

    float m0 = -1e30f, m1 = -1e30f, l0 = 0.f, l1 = 0.f;
    float oacc[8][4];
#pragma unroll
    for (int i = 0; i < 8; i++)
#pragma unroll
        for (int j = 0; j < 4; j++) oacc[i][j] = 0.f;

    issueKV(0, 0);
    CP_COMMIT();
    int ntile = S_ / 128;
    for (int ti = 0; ti < ntile; ti++) {
        int st = ti & 1;
        if (ti + 1 < ntile) { issueKV((ti + 1) * 128, (ti + 1) & 1); CP_COMMIT(); CP_WAIT1(); }
        else CP_WAIT0();
        __syncthreads();
        uint32_t bs = sb + (uint32_t)st * FSTAGE;

        uint32_t ql[4][4];
#pragma unroll
        for (int ks = 0; ks < 4; ks++)
            ldsm_x4(ql[ks], sb + QLO_BASE + qfr_off[ks]);

#pragma unroll
        for (int half = 0; half < 2; half++) {
            uint32_t hoff = (uint32_t)half * FHALF;

            float sacc[8][4];
#pragma unroll
            for (int i = 0; i < 8; i++)
#pragma unroll
                for (int j = 0; j < 4; j++) sacc[i][j] = 0.f;

#pragma unroll
            for (int ng = 0; ng < 4; ng++) {
                int nrow = ng * 16 + (lane & 7) + ((lane >> 4) & 1) * 8;
#pragma unroll
                for (int ks = 0; ks < 4; ks++) {
                    int bg = ks * 2 + ((lane >> 3) & 1);
                    uint32_t off = hoff + (uint32_t)(nrow * FROW + bg * 16);
                    uint32_t th[4], tl[4];
                    ldsm_x4(th, bs + off);
                    ldsm_x4(tl, bs + FT2 + off);
                    uint32_t bh0[2] = {th[0], th[1]}, bh1[2] = {th[2], th[3]};
                    uint32_t bl0[2] = {tl[0], tl[1]}, bl1[2] = {tl[2], tl[3]};
                    mma16816(sacc[ng * 2],     qh[ks], bh0);
                    mma16816(sacc[ng * 2],     qh[ks], bl0);
                    mma16816(sacc[ng * 2],     ql[ks], bh0);
                    mma16816(sacc[ng * 2 + 1], qh[ks], bh1);
                    mma16816(sacc[ng * 2 + 1], qh[ks], bl1);
                    mma16816(sacc[ng * 2 + 1], ql[ks], bh1);
                }
            }

            float rmax0 = -1e30f, rmax1 = -1e30f;
#pragma unroll
            for (int nt = 0; nt < 8; nt++) {
                rmax0 = fmaxf(rmax0, fmaxf(sacc[nt][0], sacc[nt][1]));
                rmax1 = fmaxf(rmax1, fmaxf(sacc[nt][2], sacc[nt][3]));
            }
            rmax0 = fmaxf(rmax0, __shfl_xor_sync(0xffffffffu, rmax0, 1));
            rmax0 = fmaxf(rmax0, __shfl_xor_sync(0xffffffffu, rmax0, 2));
            rmax1 = fmaxf(rmax1, __shfl_xor_sync(0xffffffffu, rmax1, 1));
            rmax1 = fmaxf(rmax1, __shfl_xor_sync(0xffffffffu, rmax1, 2));
            float mn0 = fmaxf(m0, rmax0), mn1 = fmaxf(m1, rmax1);
            float corr0 = __expf(m0 - mn0), corr1 = __expf(m1 - mn1);
            float ps0 = 0.f, ps1 = 0.f;
#pragma unroll
            for (int nt = 0; nt < 8; nt++) {
                sacc[nt][0] = __expf(sacc[nt][0] - mn0);
                sacc[nt][1] = __expf(sacc[nt][1] - mn0);
                sacc[nt][2] = __expf(sacc[nt][2] - mn1);
                sacc[nt][3] = __expf(sacc[nt][3] - mn1);
                ps0 += sacc[nt][0] + sacc[nt][1];
                ps1 += sacc[nt][2] + sacc[nt][3];
            }
            ps0 += __shfl_xor_sync(0xffffffffu, ps0, 1);
            ps0 += __shfl_xor_sync(0xffffffffu, ps0, 2);
            ps1 += __shfl_xor_sync(0xffffffffu, ps1, 1);
            ps1 += __shfl_xor_sync(0xffffffffu, ps1, 2);
            l0 = l0 * corr0 + ps0; l1 = l1 * corr1 + ps1;
            m0 = mn0; m1 = mn1;
#pragma unroll
            for (int i = 0; i < 8; i++) {
                oacc[i][0] *= corr0; oacc[i][1] *= corr0;
                oacc[i][2] *= corr1; oacc[i][3] *= corr1;
            }

#pragma unroll
            for (int kc = 0; kc < 4; kc++) {
                float* pa = sacc[kc * 2];
                float* pb = sacc[kc * 2 + 1];
                uint32_t phi[4], plo[4];
                phi[0] = pack_bf2(pa[0], pa[1]);
                phi[1] = pack_bf2(pa[2], pa[3]);
                phi[2] = pack_bf2(pb[0], pb[1]);
                phi[3] = pack_bf2(pb[2], pb[3]);
                {
                    __nv_bfloat162 h0 = *(__nv_bfloat162*)&phi[0];
                    __nv_bfloat162 h1 = *(__nv_bfloat162*)&phi[1];
                    __nv_bfloat162 h2 = *(__nv_bfloat162*)&phi[2];
                    __nv_bfloat162 h3 = *(__nv_bfloat162*)&phi[3];
                    plo[0] = pack_bf2(pa[0] - __bfloat162float(h0.x), pa[1] - __bfloat162float(h0.y));
                    plo[1] = pack_bf2(pa[2] - __bfloat162float(h1.x), pa[3] - __bfloat162float(h1.y));
                    plo[2] = pack_bf2(pb[0] - __bfloat162float(h2.x), pb[1] - __bfloat162float(h2.y));
                    plo[3] = pack_bf2(pb[2] - __bfloat162float(h3.x), pb[3] - __bfloat162float(h3.y));
                }
#pragma unroll
                for (int hg = 0; hg < 4; hg++) {
                    int vrow = kc * 16 + ((lane >> 3) & 1) * 8 + (lane & 7);
                    int vcol = hg * 16 + ((lane >> 4) & 1) * 8;
                    uint32_t off = hoff + (uint32_t)(vrow * FROW + vcol * 2);
                    uint32_t th[4], tl[4];
                    ldsm_x4_t(th, bs + 2 * FT2 + off);
                    ldsm_x4_t(tl, bs + 3 * FT2 + off);
                    uint32_t bh0[2] = {th[0], th[1]}, bh1[2] = {th[2], th[3]};
                    uint32_t bl0[2] = {tl[0], tl[1]}, bl1[2] = {tl[2], tl[3]};
                    mma16816(oacc[hg * 2],     phi, bh0);
                    mma16816(oacc[hg * 2],     phi, bl0);
                    mma16816(oacc[hg * 2],     plo, bh0);
                    mma16816(oacc[hg * 2 + 1], phi, bh1);
                    mma16816(oacc[hg * 2 + 1], phi, bl1);
                    mma16816(oacc[hg * 2 + 1], plo, bh1);
                }
            }
        }
        __syncthreads();
    }

    float inv0 = 1.f / l0, inv1 = 1.f / l1;
    int r0 = q0 + wid * 16 + (lane >> 2);
#pragma unroll
    for (int nt = 0; nt < 8; nt++) {
        int col = h * HD_ + nt * 8 + (lane & 3) * 2;
        float v00 = oacc[nt][0] * inv0, v01 = oacc[nt][1] * inv0;
        float v10 = oacc[nt][2] * inv1, v11 = oacc[nt][3] * inv1;
        bf16 hh, ll;
        __nv_bfloat162 ph, pl;
        split_bf16(v00, hh, ll); ph.x = hh; pl.x = ll;
        split_bf16(v01, hh, ll); ph.y = hh; pl.y = ll;
        *(__nv_bfloat162*)(Ohi + ((size_t)b_ * S_ + r0) * D_ + col) = ph;
        *(__nv_bfloat162*)(Olo + ((size_t)b_ * S_ + r0) * D_ + col) = pl;
        split_bf16(v10, hh, ll); ph.x = hh; pl.x = ll;
        split_bf16(v11, hh, ll); ph.y = hh; pl.y = ll;
        *(__nv_bfloat162*)(Ohi + ((size_t)b_ * S_ + r0 + 8) * D_ + col) = ph;
        *(__nv_bfloat162*)(Olo + ((size_t)b_ * S_ + r0 + 8) * D_ + col) = pl;
    }
}

// ---------------------------------------------------------------------------
// Launch
// ---------------------------------------------------------------------------
extern "C" void kernel_launch(void* const* d_in, const int* in_sizes, int n_in,
                              void* d_out, int out_size) {
    const float* x   = (const float*)d_in[0];
    const float* Wq  = (const float*)d_in[1];
    const float* bq  = (const float*)d_in[2];
    const float* Wk  = (const float*)d_in[3];
    const float* bk  = (const float*)d_in[4];
    const float* Wv  = (const float*)d_in[5];
    const float* bv  = (const float*)d_in[6];
    const float* Wp  = (const float*)d_in[7];
    const float* bp  = (const float*)d_in[8];
    const float* W1  = (const float*)d_in[9];
    const float* b1  = (const float*)d_in[10];
    const float* W2  = (const float*)d_in[11];
    const float* b2  = (const float*)d_in[12];
    const float* g1  = (const float*)d_in[13];
    const float* be1 = (const float*)d_in[14];
    const float* g2  = (const float*)d_in[15];
    const float* be2 = (const float*)d_in[16];
    float* out = (float*)d_out;

    bf16 *xn_hi, *xn_lo, *attn_hi, *attn_lo, *h_hi, *h_lo, *qb_hi, *qb_lo;
    bf16 *wqkv_hi, *wqkv_lo, *wp_hi, *wp_lo, *w1_hi, *w1_lo, *w2_hi, *w2_lo;
    float *bqkv, *part;
    cudaGetSymbolAddress((void**)&xn_hi, g_xn_hi);     cudaGetSymbolAddress((void**)&xn_lo, g_xn_lo);
    cudaGetSymbolAddress((void**)&attn_hi, g_attn_hi); cudaGetSymbolAddress((void**)&attn_lo, g_attn_lo);
    cudaGetSymbolAddress((void**)&h_hi, g_h_hi);       cudaGetSymbolAddress((void**)&h_lo, g_h_lo);
    cudaGetSymbolAddress((void**)&qb_hi, g_qkvb_hi);   cudaGetSymbolAddress((void**)&qb_lo, g_qkvb_lo);
    cudaGetSymbolAddress((void**)&wqkv_hi, g_wqkv_hi); cudaGetSymbolAddress((void**)&wqkv_lo, g_wqkv_lo);
    cudaGetSymbolAddress((void**)&wp_hi, g_wp_hi);     cudaGetSymbolAddress((void**)&wp_lo, g_wp_lo);
    cudaGetSymbolAddress((void**)&w1_hi, g_w1_hi);     cudaGetSymbolAddress((void**)&w1_lo, g_w1_lo);
    cudaGetSymbolAddress((void**)&w2_hi, g_w2_hi);     cudaGetSymbolAddress((void**)&w2_lo, g_w2_lo);
    cudaGetSymbolAddress((void**)&bqkv, g_bqkv);
    cudaGetSymbolAddress((void**)&part, g_part);

    cudaFuncSetAttribute(mma_gemm<2, false, false>, cudaFuncAttributeMaxDynamicSharedMemorySize, GEMM_SMEM);
    cudaFuncSetAttribute(mma_gemm<3, false, false>, cudaFuncAttributeMaxDynamicSharedMemorySize, GEMM_SMEM);
    cudaFuncSetAttribute(mma_gemm<1, true, false>,  cudaFuncAttributeMaxDynamicSharedMemorySize, GEMM_SMEM);
    cudaFuncSetAttribute(flash_mma_kernel, cudaFuncAttributeMaxDynamicSharedMemorySize, FLASH_SMEM);

    // weight conversions + bias pack + LN1, one launch
    convw_all<<<3074 + T_, dim3(32, 8)>>>(Wq, Wk, Wv, Wp, W1, W2, bq, bk, bv,
                                          wqkv_hi, wqkv_lo, wp_hi, wp_lo,
                                          w1_hi, w1_lo, w2_hi, w2_lo, bqkv,
                                          x, g1, be1, xn_hi, xn_lo);

    // fused QKV GEMM -> bf16 pairs, head-major scatter
    mma_gemm<2, false, false><<<dim3(QKV_N / 128, T_ / 128), 256, GEMM_SMEM>>>(
        xn_hi, xn_lo, wqkv_hi, wqkv_lo, bqkv, nullptr, nullptr, qb_hi, qb_lo, T_, QKV_N, D_);

    // flash attention
    flash_mma_kernel<<<dim3(S_ / 256, B_ * H_), 512, FLASH_SMEM>>>(qb_hi, qb_lo, attn_hi, attn_lo);

    // proj (split-K x2) + reduce: out = x + attn @ Wp + bp
    mma_gemm<3, false, false><<<dim3(D_ / 128, T_ / 128, 2), 256, GEMM_SMEM>>>(
        attn_hi, attn_lo, wp_hi, wp_lo, nullptr, nullptr, part, nullptr, nullptr, T_, D_, D_);
    reduce_splitk<<<(T_ * D_) / 1024, 256>>>(part, bp, x, out);

    // LN2
    ln_kernel<<<T_, 256>>>(out, g2, be2, xn_hi, xn_lo);

    // MLP1 (ReLU) -> h bf16 pair
    mma_gemm<1, true, false><<<dim3(FF_ / 128, T_ / 128), 256, GEMM_SMEM>>>(
        xn_hi, xn_lo, w1_hi, w1_lo, b1, nullptr, nullptr, h_hi, h_lo, T_, FF_, D_);

    // MLP2 (split-K x2) + reduce: out = out + h @ W2 + b2
    mma_gemm<3, false, false><<<dim3(D_ / 128, T_ / 128, 2), 256, GEMM_SMEM>>>(
        h_hi, h_lo, w2_hi, w2_lo, nullptr, nullptr, part, nullptr, nullptr, T_, D_, FF_);
    reduce_splitk<<<(T_ * D_) / 1024, 256>>>(part, b2, out, out);
}

// round 17
// speedup vs baseline: 1.0122x; 1.0049x over previous
#include <cuda_runtime.h>
#include <cuda_bf16.h>
#include <cstdint>

// Problem constants
#define B_  2
#define S_  2048
#define D_  512
#define H_  8
#define HD_ 64
#define T_  (B_*S_)      // 4096 tokens
#define FF_ (4*D_)       // 2048
#define QKV_N (3*D_)     // 1536

typedef __nv_bfloat16 bf16;

// ---------------------------------------------------------------------------
// Scratch (device globals; no allocation allowed)
// ---------------------------------------------------------------------------
__device__ bf16 g_xn_hi[T_*D_], g_xn_lo[T_*D_];             // LN out
__device__ bf16 g_qkvb_hi[3*T_*D_], g_qkvb_lo[3*T_*D_];     // head-major qkv
__device__ bf16 g_attn_hi[T_*D_], g_attn_lo[T_*D_];         // attention out [B,S,D]
__device__ bf16 g_h_hi[(size_t)T_*FF_], g_h_lo[(size_t)T_*FF_]; // MLP hidden
__device__ float g_part[2*(size_t)T_*D_];                   // split-K partials
__device__ float g_bqkv[QKV_N];
// transposed+split weights: layout [N, K] bf16
__device__ bf16 g_wqkv_hi[QKV_N*D_], g_wqkv_lo[QKV_N*D_];
__device__ bf16 g_wp_hi[D_*D_], g_wp_lo[D_*D_];
__device__ bf16 g_w1_hi[D_*FF_], g_w1_lo[D_*FF_];
__device__ bf16 g_w2_hi[D_*FF_], g_w2_lo[D_*FF_];

// ---------------------------------------------------------------------------
// helpers
// ---------------------------------------------------------------------------
__device__ __forceinline__ uint32_t smem_to_u32(const void* p) {
    uint32_t a;
    asm("{ .reg .u64 tmp; cvta.to.shared.u64 tmp, %1; cvt.u32.u64 %0, tmp; }"
        : "=r"(a) : "l"(p));
    return a;
}
__device__ __forceinline__ void cp16(uint32_t smem, const void* g) {
    asm volatile("cp.async.ca.shared.global [%0], [%1], 16;" :: "r"(smem), "l"(g));
}
#define CP_COMMIT() asm volatile("cp.async.commit_group;" ::: "memory")
#define CP_WAIT2()  asm volatile("cp.async.wait_group 2;" ::: "memory")
#define CP_WAIT1()  asm volatile("cp.async.wait_group 1;" ::: "memory")
#define CP_WAIT0()  asm volatile("cp.async.wait_group 0;" ::: "memory")

__device__ __forceinline__ void ldsm_x4(uint32_t* r, uint32_t addr) {
    asm volatile("ldmatrix.sync.aligned.m8n8.x4.shared.b16 {%0,%1,%2,%3}, [%4];"
        : "=r"(r[0]), "=r"(r[1]), "=r"(r[2]), "=r"(r[3]) : "r"(addr));
}
__device__ __forceinline__ void ldsm_x4_t(uint32_t* r, uint32_t addr) {
    asm volatile("ldmatrix.sync.aligned.m8n8.x4.trans.shared.b16 {%0,%1,%2,%3}, [%4];"
        : "=r"(r[0]), "=r"(r[1]), "=r"(r[2]), "=r"(r[3]) : "r"(addr));
}
__device__ __forceinline__ void mma16816(float* c, const uint32_t* a, const uint32_t* b) {
    asm volatile("mma.sync.aligned.m16n8k16.row.col.f32.bf16.bf16.f32 "
        "{%0,%1,%2,%3}, {%4,%5,%6,%7}, {%8,%9}, {%0,%1,%2,%3};"
        : "+f"(c[0]), "+f"(c[1]), "+f"(c[2]), "+f"(c[3])
        : "r"(a[0]), "r"(a[1]), "r"(a[2]), "r"(a[3]), "r"(b[0]), "r"(b[1]));
}
__device__ __forceinline__ void split_bf16(float v, bf16& h, bf16& l) {
    h = __float2bfloat16(v);
    l = __float2bfloat16(v - __bfloat162float(h));
}
__device__ __forceinline__ uint32_t pack_bf2(float a, float b) {
    __nv_bfloat162 p;
    p.x = __float2bfloat16(a);
    p.y = __float2bfloat16(b);
    return *(uint32_t*)&p;
}
// swizzled byte offset within a 128row x 64B tile (rows of 4 x 16B groups)
__device__ __forceinline__ uint32_t sw_off(int row, int g) {
    return (uint32_t)(((row << 2) | (g ^ ((row >> 1) & 3))) << 4);
}

// ---------------------------------------------------------------------------
// LN math on two per-thread values (flat 256-thread block)
// ---------------------------------------------------------------------------
__device__ __forceinline__ void ln_vals(float v0, float v1, const float* __restrict__ g,
                                        const float* __restrict__ be, bf16* __restrict__ hi,
                                        bf16* __restrict__ lo, int row, int t) {
    float s = v0 + v1, ss = v0 * v0 + v1 * v1;
#pragma unroll
    for (int o = 16; o > 0; o >>= 1) {
        s  += __shfl_xor_sync(0xffffffffu, s, o);
        ss += __shfl_xor_sync(0xffffffffu, ss, o);
    }
    __shared__ float rs[8], rss[8];
    if ((t & 31) == 0) { rs[t >> 5] = s; rss[t >> 5] = ss; }
    __syncthreads();
    s = 0.f; ss = 0.f;
#pragma unroll
    for (int i = 0; i < 8; i++) { s += rs[i]; ss += rss[i]; }
    float mean = s * (1.f / (float)D_);
    float var  = ss * (1.f / (float)D_) - mean * mean;
    float r = rsqrtf(var + 1e-5f);
    float y0 = (v0 - mean) * r * g[t] + be[t];
    float y1 = (v1 - mean) * r * g[t + 256] + be[t + 256];
    bf16 h, l;
    split_bf16(y0, h, l); hi[(size_t)row * D_ + t] = h;       lo[(size_t)row * D_ + t] = l;
    split_bf16(y1, h, l); hi[(size_t)row * D_ + t + 256] = h; lo[(size_t)row * D_ + t + 256] = l;
}

__device__ __forceinline__ void ln_row(const float* __restrict__ x, const float* __restrict__ g,
                                       const float* __restrict__ be, bf16* __restrict__ hi,
                                       bf16* __restrict__ lo, int row, int t) {
    const float* xr = x + (size_t)row * D_;
    ln_vals(xr[t], xr[t + 256], g, be, hi, lo, row, t);
}

// ---------------------------------------------------------------------------
// Fused prologue: weight transposes + bias pack + LN1 in ONE launch.
// ---------------------------------------------------------------------------
__global__ void convw_all(
    const float* __restrict__ Wq, const float* __restrict__ Wk, const float* __restrict__ Wv,
    const float* __restrict__ Wp, const float* __restrict__ W1, const float* __restrict__ W2,
    const float* __restrict__ bq, const float* __restrict__ bk, const float* __restrict__ bv,
    bf16* __restrict__ qkv_hi, bf16* __restrict__ qkv_lo,
    bf16* __restrict__ wp_hi, bf16* __restrict__ wp_lo,
    bf16* __restrict__ w1_hi, bf16* __restrict__ w1_lo,
    bf16* __restrict__ w2_hi, bf16* __restrict__ w2_lo,
    float* __restrict__ bqkv,
    const float* __restrict__ x, const float* __restrict__ g1,
    const float* __restrict__ be1, bf16* __restrict__ xn_hi, bf16* __restrict__ xn_lo) {
    int bid = blockIdx.x;
    int tx = threadIdx.x, ty = threadIdx.y;   // 32 x 8
    int ft = ty * 32 + tx;

    if (bid >= 3074) {                        // LN1 rows
        ln_row(x, g1, be1, xn_hi, xn_lo, bid - 3074, ft);
        return;
    }
    if (bid >= 3072) {                        // bias pack
        int t = (bid - 3072) * 256 + ft;
        if (t < D_) { bqkv[t] = bq[t]; bqkv[t + D_] = bk[t]; bqkv[t + 2 * D_] = bv[t]; }
        return;
    }

    const float* src; int sld; bf16 *dh, *dl; int dld; int kb, nb;
    if (bid < 768) {
        int w = bid >> 8, r = bid & 255;
        int h = r >> 5, rr = r & 31;
        int kbi = rr >> 1, nbi = rr & 1;
        const float* W = (w == 0) ? Wq : (w == 1) ? Wk : Wv;
        src = W + (size_t)h * D_ * HD_; sld = HD_;
        kb = kbi * 32; nb = nbi * 32;
        size_t rowoff = ((size_t)w * D_ + h * HD_) * D_;
        dh = qkv_hi + rowoff; dl = qkv_lo + rowoff; dld = D_;
    } else if (bid < 1024) {
        int r = bid - 768;
        kb = (r >> 4) * 32; nb = (r & 15) * 32;
        src = Wp; sld = D_; dh = wp_hi; dl = wp_lo; dld = D_;
    } else if (bid < 2048) {
        int r = bid - 1024;
        kb = (r >> 6) * 32; nb = (r & 63) * 32;
        src = W1; sld = FF_; dh = w1_hi; dl = w1_lo; dld = D_;
    } else {
        int r = bid - 2048;
        kb = (r >> 4) * 32; nb = (r & 15) * 32;
        src = W2; sld = D_; dh = w2_hi; dl = w2_lo; dld = FF_;
    }

    __shared__ float t[32][33];
#pragma unroll
    for (int i = 0; i < 32; i += 8) t[ty + i][tx] = src[(size_t)(kb + ty + i) * sld + nb + tx];
    __syncthreads();
#pragma unroll
    for (int i = 0; i < 32; i += 8) {
        float v = t[tx][ty + i];
        size_t o = (size_t)(nb + ty + i) * dld + kb + tx;
        bf16 h, l; split_bf16(v, h, l);
        dh[o] = h; dl[o] = l;
    }
}

// ---------------------------------------------------------------------------
// Fused split-K reduce + LN2: out = p0+p1+bias+res, then LN -> xn pair.
// One block per row, 256 threads.
// ---------------------------------------------------------------------------
__global__ void reduce_ln(const float* __restrict__ part, const float* __restrict__ bias,
                          const float* __restrict__ res, const float* __restrict__ g,
                          const float* __restrict__ be, float* __restrict__ out,
                          bf16* __restrict__ hi, bf16* __restrict__ lo) {
    int row = blockIdx.x, t = threadIdx.x;
    size_t base = (size_t)row * D_;
    float v0 = part[base + t]       + part[(size_t)T_ * D_ + base + t]
             + res[base + t]        + bias[t];
    float v1 = part[base + t + 256] + part[(size_t)T_ * D_ + base + t + 256]
             + res[base + t + 256]  + bias[t + 256];
    out[base + t] = v0;
    out[base + t + 256] = v1;
    ln_vals(v0, v1, g, be, hi, lo, row, t);
}

// ---------------------------------------------------------------------------
// Split-K reduce (final output): out = part0 + part1 + bias + res.
// ---------------------------------------------------------------------------
__global__ void reduce_splitk(const float* __restrict__ part, const float* __restrict__ bias,
                              const float* __restrict__ res, float* __restrict__ out) {
    size_t i = ((size_t)blockIdx.x * 256 + threadIdx.x) * 4;
    float4 a = *(const float4*)(part + i);
    float4 b = *(const float4*)(part + (size_t)T_ * D_ + i);
    float4 r = *(const float4*)(res + i);
    int col = (int)(i & (D_ - 1));
    float4 bs = *(const float4*)(bias + col);
    float4 o;
    o.x = a.x + b.x + r.x + bs.x;
    o.y = a.y + b.y + r.y + bs.y;
    o.z = a.z + b.z + r.z + bs.z;
    o.w = a.w + b.w + r.w + bs.w;
    *(float4*)(out + i) = o;
}

// ---------------------------------------------------------------------------
// mma.sync GEMM, bf16x3, 3-stage cp.async pipeline. 256 threads, warp grid
// 2(m)x4(n), warp tile 64x32, 2 CTA/SM.
// MODE 1: bf16 pair out (RELU opt). MODE 2: qkv scatter.
// MODE 3: split-K partial (gridDim.z=2, raw fp32 to Cf+z*M*N).
// ---------------------------------------------------------------------------
#define SMT_AHI 0
#define SMT_ALO 8192
#define SMT_BHI 16384
#define SMT_BLO 24576
#define GSTAGE  32768
#define GEMM_SMEM (3*GSTAGE)

template <int MODE, bool RELU>
__global__ void __launch_bounds__(256, 2) mma_gemm(
    const bf16* __restrict__ Ahi, const bf16* __restrict__ Alo,
    const bf16* __restrict__ Bhi, const bf16* __restrict__ Blo,
    const float* __restrict__ bias,
    float* __restrict__ Cf, bf16* __restrict__ Chi, bf16* __restrict__ Clo,
    int M, int N, int K) {
    extern __shared__ __align__(128) char smem_buf[];
    uint32_t sb = smem_to_u32(smem_buf);
    int tid = threadIdx.x, lane = tid & 31, wid = tid >> 5;
    int wm = wid >> 2, wn = wid & 3;
    int m0 = blockIdx.y * 128, n0 = blockIdx.x * 128;
    int kbase = (MODE == 3) ? (int)blockIdx.z * (K >> 1) : 0;
    int klen  = (MODE == 3) ? (K >> 1) : K;

    float acc[4][4][4];
#pragma unroll
    for (int a = 0; a < 4; a++)
#pragma unroll
        for (int b = 0; b < 4; b++)
#pragma unroll
            for (int cc = 0; cc < 4; cc++) acc[a][b][cc] = 0.f;

    int ldrow = tid >> 2, ldg_ = tid & 3;
    int nchunk = klen >> 5;

    auto issue = [&](int c) {
        int k0 = kbase + (c << 5);
        uint32_t base = sb + (uint32_t)(c % 3) * GSTAGE;
#pragma unroll
        for (int it = 0; it < 2; it++) {
            int row = ldrow + it * 64;
            uint32_t off = sw_off(row, ldg_);
            size_t ao = (size_t)(m0 + row) * K + k0 + ldg_ * 8;
            size_t bo = (size_t)(n0 + row) * K + k0 + ldg_ * 8;
            cp16(base + SMT_AHI + off, Ahi + ao);
            cp16(base + SMT_ALO + off, Alo + ao);
            cp16(base + SMT_BHI + off, Bhi + bo);
            cp16(base + SMT_BLO + off, Blo + bo);
        }
    };

    issue(0); CP_COMMIT();
    if (nchunk > 1) { issue(1); CP_COMMIT(); }
    for (int c = 0; c < nchunk; c++) {
        if (c + 2 < nchunk) { issue(c + 2); CP_COMMIT(); CP_WAIT2(); }
        else if (c + 1 < nchunk) CP_WAIT1();
        else CP_WAIT0();
        __syncthreads();
        uint32_t base = sb + (uint32_t)(c % 3) * GSTAGE;
#pragma unroll
        for (int ks = 0; ks < 2; ks++) {
            int kg = ks * 2;
            uint32_t bh[4][2], bl[4][2];
#pragma unroll
            for (int ntp = 0; ntp < 2; ntp++) {
                int nrow = wn * 32 + ntp * 16 + (lane & 7) + ((lane >> 4) & 1) * 8;
                int bg = kg + ((lane >> 3) & 1);
                uint32_t off = sw_off(nrow, bg);
                uint32_t t4[4];
                ldsm_x4(t4, base + SMT_BHI + off);
                bh[ntp * 2][0] = t4[0]; bh[ntp * 2][1] = t4[1];
                bh[ntp * 2 + 1][0] = t4[2]; bh[ntp * 2 + 1][1] = t4[3];
                ldsm_x4(t4, base + SMT_BLO + off);
                bl[ntp * 2][0] = t4[0]; bl[ntp * 2][1] = t4[1];
                bl[ntp * 2 + 1][0] = t4[2]; bl[ntp * 2 + 1][1] = t4[3];
            }
#pragma unroll
            for (int mt = 0; mt < 4; mt++) {
                int arow = wm * 64 + mt * 16 + (lane & 7) + ((lane >> 3) & 1) * 8;
                int ag = kg + (lane >> 4);
                uint32_t off = sw_off(arow, ag);
                uint32_t ah[4], al[4];
                ldsm_x4(ah, base + SMT_AHI + off);
                ldsm_x4(al, base + SMT_ALO + off);
#pragma unroll
                for (int nt = 0; nt < 4; nt++) {
                    mma16816(acc[mt][nt], ah, bh[nt]);
                    mma16816(acc[mt][nt], ah, bl[nt]);
                    mma16816(acc[mt][nt], al, bh[nt]);
                }
            }
        }
        __syncthreads();
    }

#pragma unroll
    for (int mt = 0; mt < 4; mt++) {
#pragma unroll
        for (int nt = 0; nt < 4; nt++) {
            int r0 = m0 + wm * 64 + mt * 16 + (lane >> 2);
            int col = n0 + wn * 32 + nt * 8 + (lane & 3) * 2;
            if (MODE == 3) {
                float* dst = Cf + (size_t)blockIdx.z * M * N;
                float2 o0 = {acc[mt][nt][0], acc[mt][nt][1]};
                float2 o1 = {acc[mt][nt][2], acc[mt][nt][3]};
                *(float2*)(dst + (size_t)r0 * N + col) = o0;
                *(float2*)(dst + (size_t)(r0 + 8) * N + col) = o1;
                continue;
            }
            float b0 = __ldg(bias + col), b1 = __ldg(bias + col + 1);
            float v00 = acc[mt][nt][0] + b0, v01 = acc[mt][nt][1] + b1;
            float v10 = acc[mt][nt][2] + b0, v11 = acc[mt][nt][3] + b1;
            if (RELU) {
                v00 = fmaxf(v00, 0.f); v01 = fmaxf(v01, 0.f);
                v10 = fmaxf(v10, 0.f); v11 = fmaxf(v11, 0.f);
            }
            if (MODE == 1) {
                bf16 h, l;
                __nv_bfloat162 ph, pl;
                split_bf16(v00, h, l); ph.x = h; pl.x = l;
                split_bf16(v01, h, l); ph.y = h; pl.y = l;
                *(__nv_bfloat162*)(Chi + (size_t)r0 * N + col) = ph;
                *(__nv_bfloat162*)(Clo + (size_t)r0 * N + col) = pl;
                split_bf16(v10, h, l); ph.x = h; pl.x = l;
                split_bf16(v11, h, l); ph.y = h; pl.y = l;
                *(__nv_bfloat162*)(Chi + (size_t)(r0 + 8) * N + col) = ph;
                *(__nv_bfloat162*)(Clo + (size_t)(r0 + 8) * N + col) = pl;
            } else {
                int which = col >> 9, rem = col & 511;
                int hh2 = rem >> 6, e = rem & 63;
#pragma unroll
                for (int rr = 0; rr < 2; rr++) {
                    int t = r0 + rr * 8;
                    float va = rr ? v10 : v00, vb = rr ? v11 : v01;
                    size_t off = (size_t)which * (T_ * (size_t)D_) +
                                 (((size_t)(t >> 11) * H_ + hh2) * S_ + (t & (S_ - 1))) * HD_ + e;
                    bf16 h, l;
                    __nv_bfloat162 ph, pl;
                    split_bf16(va, h, l); ph.x = h; pl.x = l;
                    split_bf16(vb, h, l); ph.y = h; pl.y = l;
                    *(__nv_bfloat162*)(Chi + off) = ph;
                    *(__nv_bfloat162*)(Clo + off) = pl;
                }
            }
        }
    }
}

// ---------------------------------------------------------------------------
// Flash attention, tensor cores, bf16x3 (R13 428.0 version). Q-tile 256 rows,
// 512 threads, Q-lo persistent in smem. KV staged 128 rows per cp.async
// group (2 stages), computed as two 64-row halves.
// ---------------------------------------------------------------------------
#define FPAD 72                          // bf16 per row (144 B)
#define FROW (FPAD*2)                    // 144 B
#define FHALF (64*FROW)                  // 9216 B (64-row half-tile)
#define FT2 (128*FROW)                   // 18432 B (128-row tile)
#define FSTAGE (4*FT2)                   // K_HI,K_LO,V_HI,V_LO = 73728 B
#define QLO_BASE (2*FSTAGE)              // persistent Q-lo region (256 rows)
#define FLASH_SMEM (2*FSTAGE + 256*FROW) // 184320 B

__global__ void __launch_bounds__(512, 1) flash_mma_kernel(
    const bf16* __restrict__ Phi, const bf16* __restrict__ Plo,
    bf16* __restrict__ Ohi, bf16* __restrict__ Olo) {
    extern __shared__ __align__(16) char fsm[];
    uint32_t sb = smem_to_u32(fsm);
    int tid = threadIdx.x, lane = tid & 31, wid = tid >> 5;
    int bh = blockIdx.y;
    int b_ = bh >> 3, h = bh & 7;
    int q0 = blockIdx.x * 256;

    size_t headoff = ((size_t)(b_ * H_ + h) * S_) * HD_;
    const bf16* Qh = Phi + headoff + (size_t)q0 * HD_;
    const bf16* Ql = Plo + headoff + (size_t)q0 * HD_;
    const bf16* Kh = Phi + (size_t)T_ * D_ + headoff;
    const bf16* Kl = Plo + (size_t)T_ * D_ + headoff;
    const bf16* Vh = Phi + 2 * (size_t)T_ * D_ + headoff;
    const bf16* Vl = Plo + 2 * (size_t)T_ * D_ + headoff;

#pragma unroll
    for (int it = 0; it < 4; it++) {
        int idx = it * 512 + tid;          // 0..2047
        int row = idx >> 3, fg = idx & 7;
        uint32_t off = (uint32_t)(row * FROW + fg * 16);
        *(uint4*)(fsm + off)            = *(const uint4*)(Qh + (size_t)row * HD_ + fg * 8);
        *(uint4*)(fsm + QLO_BASE + off) = *(const uint4*)(Ql + (size_t)row * HD_ + fg * 8);
    }
    __syncthreads();
    uint32_t qh[4][4];
    int arow = wid * 16 + (lane & 7) + ((lane >> 3) & 1) * 8;
    uint32_t qfr_off[4];
#pragma unroll
    for (int ks = 0; ks < 4; ks++) {
        qfr_off[ks] = (uint32_t)(arow * FROW + (ks * 2 + (lane >> 4)) * 16);
        ldsm_x4(qh[ks], sb + qfr_off[ks]);
    }
    __syncthreads();

    auto issueKV = [&](int kv, int st) {
        uint32_t bs = sb + (uint32_t)st * FSTAGE;
#pragma unroll
        for (int it = 0; it < 2; it++) {
            int idx = it * 512 + tid;      // 0..1023 -> 128 rows x 8 groups
            int row = idx >> 3, fg = idx & 7;
            uint32_t off = (uint32_t)(row * FROW + fg * 16);
            size_t go = (size_t)(kv + row) * HD_ + fg * 8;
            cp16(bs + off,           Kh + go);
            cp16(bs + FT2 + off,     Kl + go);
            cp16(bs + 2 * FT2 + off, Vh + go);
            cp16(bs + 3 * FT2 + off, Vl + go);
        }
    };

    float m0 = -1e30f, m1 = -1e30f, l0 = 0.f, l1 = 0.f;
    float oacc[8][4];
#pragma unroll
    for (int i = 0; i < 8; i++)
#pragma unroll
        for (int j = 0; j < 4; j++) oacc[i][j] = 0.f;

    issueKV(0, 0);
    CP_COMMIT();
    int ntile = S_ / 128;
    for (int ti = 0; ti < ntile; ti++) {
        int st = ti & 1;
        if (ti + 1 < ntile) { issueKV((ti + 1) * 128, (ti + 1) & 1); CP_COMMIT(); CP_WAIT1(); }
        else CP_WAIT0();
        __syncthreads();
        uint32_t bs = sb + (uint32_t)st * FSTAGE;

        uint32_t ql[4][4];
#pragma unroll
        for (int ks = 0; ks < 4; ks++)
            ldsm_x4(ql[ks], sb + QLO_BASE + qfr_off[ks]);

#pragma unroll
        for (int half = 0; half < 2; half++) {
            uint32_t hoff = (uint32_t)half * FHALF;

            float sacc[8][4];
#pragma unroll
            for (int i = 0; i < 8; i++)
#pragma unroll
                for (int j = 0; j < 4; j++) sacc[i][j] = 0.f;

#pragma unroll
            for (int ng = 0; ng < 4; ng++) {
                int nrow = ng * 16 + (lane & 7) + ((lane >> 4) & 1) * 8;
#pragma unroll
                for (int ks = 0; ks < 4; ks++) {
                    int bg = ks * 2 + ((lane >> 3) & 1);
                    uint32_t off = hoff + (uint32_t)(nrow * FROW + bg * 16);
                    uint32_t th[4], tl[4];
                    ldsm_x4(th, bs + off);
                    ldsm_x4(tl, bs + FT2 + off);
                    uint32_t bh0[2] = {th[0], th[1]}, bh1[2] = {th[2], th[3]};
                    uint32_t bl0[2] = {tl[0], tl[1]}, bl1[2] = {tl[2], tl[3]};
                    mma16816(sacc[ng * 2],     qh[ks], bh0);
                    mma16816(sacc[ng * 2],     qh[ks], bl0);
                    mma16816(sacc[ng * 2],     ql[ks], bh0);
                    mma16816(sacc[ng * 2 + 1], qh[ks], bh1);
                    mma16816(sacc[ng * 2 + 1], qh[ks], bl1);
                    mma16816(sacc[ng * 2 + 1], ql[ks], bh1);
                }
            }

            float rmax0 = -1e30f, rmax1 = -1e30f;
#pragma unroll
            for (int nt = 0; nt < 8; nt++) {
                rmax0 = fmaxf(rmax0, fmaxf(sacc[nt][0], sacc[nt][1]));
                rmax1 = fmaxf(rmax1, fmaxf(sacc[nt][2], sacc[nt][3]));
            }
            rmax0 = fmaxf(rmax0, __shfl_xor_sync(0xffffffffu, rmax0, 1));
            rmax0 = fmaxf(rmax0, __shfl_xor_sync(0xffffffffu, rmax0, 2));
            rmax1 = fmaxf(rmax1, __shfl_xor_sync(0xffffffffu, rmax1, 1));
            rmax1 = fmaxf(rmax1, __shfl_xor_sync(0xffffffffu, rmax1, 2));
            float mn0 = fmaxf(m0, rmax0), mn1 = fmaxf(m1, rmax1);
            float corr0 = __expf(m0 - mn0), corr1 = __expf(m1 - mn1);
            float ps0 = 0.f, ps1 = 0.f;
#pragma unroll
            for (int nt = 0; nt < 8; nt++) {
                sacc[nt][0] = __expf(sacc[nt][0] - mn0);
                sacc[nt][1] = __expf(sacc[nt][1] - mn0);
                sacc[nt][2] = __expf(sacc[nt][2] - mn1);
                sacc[nt][3] = __expf(sacc[nt][3] - mn1);
                ps0 += sacc[nt][0] + sacc[nt][1];
                ps1 += sacc[nt][2] + sacc[nt][3];
            }
            ps0 += __shfl_xor_sync(0xffffffffu, ps0, 1);
            ps0 += __shfl_xor_sync(0xffffffffu, ps0, 2);
            ps1 += __shfl_xor_sync(0xffffffffu, ps1, 1);
            ps1 += __shfl_xor_sync(0xffffffffu, ps1, 2);
            l0 = l0 * corr0 + ps0; l1 = l1 * corr1 + ps1;
            m0 = mn0; m1 = mn1;
#pragma unroll
            for (int i = 0; i < 8; i++) {
                oacc[i][0] *= corr0; oacc[i][1] *= corr0;
                oacc[i][2] *= corr1; oacc[i][3] *= corr1;
            }

#pragma unroll
            for (int kc = 0; kc < 4; kc++) {
                float* pa = sacc[kc * 2];
                float* pb = sacc[kc * 2 + 1];
                uint32_t phi[4], plo[4];
                phi[0] = pack_bf2(pa[0], pa[1]);
                phi[1] = pack_bf2(pa[2], pa[3]);
                phi[2] = pack_bf2(pb[0], pb[1]);
                phi[3] = pack_bf2(pb[2], pb[3]);
                {
                    __nv_bfloat162 h0 = *(__nv_bfloat162*)&phi[0];
                    __nv_bfloat162 h1 = *(__nv_bfloat162*)&phi[1];
                    __nv_bfloat162 h2 = *(__nv_bfloat162*)&phi[2];
                    __nv_bfloat162 h3 = *(__nv_bfloat162*)&phi[3];
                    plo[0] = pack_bf2(pa[0] - __bfloat162float(h0.x), pa[1] - __bfloat162float(h0.y));
                    plo[1] = pack_bf2(pa[2] - __bfloat162float(h1.x), pa[3] - __bfloat162float(h1.y));
                    plo[2] = pack_bf2(pb[0] - __bfloat162float(h2.x), pb[1] - __bfloat162float(h2.y));
                    plo[3] = pack_bf2(pb[2] - __bfloat162float(h3.x), pb[3] - __bfloat162float(h3.y));
                }
#pragma unroll
                for (int hg = 0; hg < 4; hg++) {
                    int vrow = kc * 16 + ((lane >> 3) & 1) * 8 + (lane & 7);
                    int vcol = hg * 16 + ((lane >> 4) & 1) * 8;
                    uint32_t off = hoff + (uint32_t)(vrow * FROW + vcol * 2);
                    uint32_t th[4], tl[4];
                    ldsm_x4_t(th, bs + 2 * FT2 + off);
                    ldsm_x4_t(tl, bs + 3 * FT2 + off);
                    uint32_t bh0[2] = {th[0], th[1]}, bh1[2] = {th[2], th[3]};
                    uint32_t bl0[2] = {tl[0], tl[1]}, bl1[2] = {tl[2], tl[3]};
                    mma16816(oacc[hg * 2],     phi, bh0);
                    mma16816(oacc[hg * 2],     phi, bl0);
                    mma16816(oacc[hg * 2],     plo, bh0);
                    mma16816(oacc[hg * 2 + 1], phi, bh1);
                    mma16816(oacc[hg * 2 + 1], phi, bl1);
                    mma16816(oacc[hg * 2 + 1], plo, bh1);
                }
            }
        }
        __syncthreads();
    }

    float inv0 = 1.f / l0, inv1 = 1.f / l1;
    int r0 = q0 + wid * 16 + (lane >> 2);
#pragma unroll
    for (int nt = 0; nt < 8; nt++) {
        int col = h * HD_ + nt * 8 + (lane & 3) * 2;
        float v00 = oacc[nt][0] * inv0, v01 = oacc[nt][1] * inv0;
        float v10 = oacc[nt][2] * inv1, v11 = oacc[nt][3] * inv1;
        bf16 hh, ll;
        __nv_bfloat162 ph, pl;
        split_bf16(v00, hh, ll); ph.x = hh; pl.x = ll;
        split_bf16(v01, hh, ll); ph.y = hh; pl.y = ll;
        *(__nv_bfloat162*)(Ohi + ((size_t)b_ * S_ + r0) * D_ + col) = ph;
        *(__nv_bfloat162*)(Olo + ((size_t)b_ * S_ + r0) * D_ + col) = pl;
        split_bf16(v10, hh, ll); ph.x = hh; pl.x = ll;
        split_bf16(v11, hh, ll); ph.y = hh; pl.y = ll;
        *(__nv_bfloat162*)(Ohi + ((size_t)b_ * S_ + r0 + 8) * D_ + col) = ph;
        *(__nv_bfloat162*)(Olo + ((size_t)b_ * S_ + r0 + 8) * D_ + col) = pl;
    }
}

// ---------------------------------------------------------------------------
// Launch
// ---------------------------------------------------------------------------
extern "C" void kernel_launch(void* const* d_in, const int* in_sizes, int n_in,
                              void* d_out, int out_size) {
    const float* x   = (const float*)d_in[0];
    const float* Wq  = (const float*)d_in[1];
    const float* bq  = (const float*)d_in[2];
    const float* Wk  = (const float*)d_in[3];
    const float* bk  = (const float*)d_in[4];
    const float* Wv  = (const float*)d_in[5];
    const float* bv  = (const float*)d_in[6];
    const float* Wp  = (const float*)d_in[7];
    const float* bp  = (const float*)d_in[8];
    const float* W1  = (const float*)d_in[9];
    const float* b1  = (const float*)d_in[10];
    const float* W2  = (const float*)d_in[11];
    const float* b2  = (const float*)d_in[12];
    const float* g1  = (const float*)d_in[13];
    const float* be1 = (const float*)d_in[14];
    const float* g2  = (const float*)d_in[15];
    const float* be2 = (const float*)d_in[16];
    float* out = (float*)d_out;

    bf16 *xn_hi, *xn_lo, *attn_hi, *attn_lo, *h_hi, *h_lo, *qb_hi, *qb_lo;
    bf16 *wqkv_hi, *wqkv_lo, *wp_hi, *wp_lo, *w1_hi, *w1_lo, *w2_hi, *w2_lo;
    float *bqkv, *part;
    cudaGetSymbolAddress((void**)&xn_hi, g_xn_hi);     cudaGetSymbolAddress((void**)&xn_lo, g_xn_lo);
    cudaGetSymbolAddress((void**)&attn_hi, g_attn_hi); cudaGetSymbolAddress((void**)&attn_lo, g_attn_lo);
    cudaGetSymbolAddress((void**)&h_hi, g_h_hi);       cudaGetSymbolAddress((void**)&h_lo, g_h_lo);
    cudaGetSymbolAddress((void**)&qb_hi, g_qkvb_hi);   cudaGetSymbolAddress((void**)&qb_lo, g_qkvb_lo);
    cudaGetSymbolAddress((void**)&wqkv_hi, g_wqkv_hi); cudaGetSymbolAddress((void**)&wqkv_lo, g_wqkv_lo);
    cudaGetSymbolAddress((void**)&wp_hi, g_wp_hi);     cudaGetSymbolAddress((void**)&wp_lo, g_wp_lo);
    cudaGetSymbolAddress((void**)&w1_hi, g_w1_hi);     cudaGetSymbolAddress((void**)&w1_lo, g_w1_lo);
    cudaGetSymbolAddress((void**)&w2_hi, g_w2_hi);     cudaGetSymbolAddress((void**)&w2_lo, g_w2_lo);
    cudaGetSymbolAddress((void**)&bqkv, g_bqkv);
    cudaGetSymbolAddress((void**)&part, g_part);

    cudaFuncSetAttribute(mma_gemm<2, false>, cudaFuncAttributeMaxDynamicSharedMemorySize, GEMM_SMEM);
    cudaFuncSetAttribute(mma_gemm<3, false>, cudaFuncAttributeMaxDynamicSharedMemorySize, GEMM_SMEM);
    cudaFuncSetAttribute(mma_gemm<1, true>,  cudaFuncAttributeMaxDynamicSharedMemorySize, GEMM_SMEM);
    cudaFuncSetAttribute(flash_mma_kernel, cudaFuncAttributeMaxDynamicSharedMemorySize, FLASH_SMEM);

    // weight conversions + bias pack + LN1, one launch
    convw_all<<<3074 + T_, dim3(32, 8)>>>(Wq, Wk, Wv, Wp, W1, W2, bq, bk, bv,
                                          wqkv_hi, wqkv_lo, wp_hi, wp_lo,
                                          w1_hi, w1_lo, w2_hi, w2_lo, bqkv,
                                          x, g1, be1, xn_hi, xn_lo);

    // fused QKV GEMM -> bf16 pairs, head-major scatter
    mma_gemm<2, false><<<dim3(QKV_N / 128, T_ / 128), 256, GEMM_SMEM>>>(
        xn_hi, xn_lo, wqkv_hi, wqkv_lo, bqkv, nullptr, qb_hi, qb_lo, T_, QKV_N, D_);

    // flash attention
    flash_mma_kernel<<<dim3(S_ / 256, B_ * H_), 512, FLASH_SMEM>>>(qb_hi, qb_lo, attn_hi, attn_lo);

    // proj (split-K x2), then FUSED reduce + LN2 in one pass
    mma_gemm<3, false><<<dim3(D_ / 128, T_ / 128, 2), 256, GEMM_SMEM>>>(
        attn_hi, attn_lo, wp_hi, wp_lo, nullptr, part, nullptr, nullptr, T_, D_, D_);
    reduce_ln<<<T_, 256>>>(part, bp, x, g2, be2, out, xn_hi, xn_lo);

    // MLP1 (ReLU) -> h bf16 pair
    mma_gemm<1, true><<<dim3(FF_ / 128, T_ / 128), 256, GEMM_SMEM>>>(
        xn_hi, xn_lo, w1_hi, w1_lo, b1, nullptr, h_hi, h_lo, T_, FF_, D_);

    // MLP2 (split-K x2) + reduce: out = out + h @ W2 + b2
    mma_gemm<3, false><<<dim3(D_ / 128, T_ / 128, 2), 256, GEMM_SMEM>>>(
        h_hi, h_lo, w2_hi, w2_lo, nullptr, part, nullptr, nullptr, T_, D_, FF_);
    reduce_splitk<<<(T_ * D_) / 1024, 256>>>(part, b2, out, out);
}